// round 4
// baseline (speedup 1.0000x reference)
#include <cuda_runtime.h>
#include <math.h>

#define NPOS 49
#define DIMV 512
#define DHALF 256
#define EDIM 48
#define BWIN 512
#define TOK_PER_G 25088            // 512*49
#define SLAB 12845056              // 25088*512
#define WSZ 262144                 // 512*512

// ---------------- device scratch (no allocations allowed) ----------------
__device__ float g_xz[51380224];   // (2048, 49, 512)
__device__ float g_ycat[51380224]; // (2048, 49, 512)
__device__ float g_Wc[4 * WSZ];
__device__ float g_Wo[4 * WSZ];
__device__ float g_bc[4 * DIMV];
__device__ float g_outb[DIMV];
__device__ float g_gates[4];

__constant__ int c_diag[49] = {0,1,7,2,8,14,3,9,15,21,4,10,16,22,28,5,11,17,23,29,35,
                               6,12,18,24,30,36,42,13,19,25,31,37,43,20,26,32,38,44,
                               27,33,39,45,34,40,46,41,47,48};
__constant__ int c_anti[49] = {6,5,13,4,12,20,3,11,19,27,2,10,18,26,34,1,9,17,25,33,41,
                               0,8,16,24,32,40,48,7,15,23,31,39,47,14,22,30,38,46,
                               21,29,37,45,28,36,44,35,43,42};

// ---------------- small prep kernels ----------------
__global__ void gates_kernel(const float* __restrict__ gl) {
    if (threadIdx.x == 0) {
        float m = fmaxf(fmaxf(gl[0], gl[1]), fmaxf(gl[2], gl[3]));
        float e0 = expf(gl[0] - m), e1 = expf(gl[1] - m), e2 = expf(gl[2] - m), e3 = expf(gl[3] - m);
        float s = e0 + e1 + e2 + e3;
        g_gates[0] = e0 / s; g_gates[1] = e1 / s; g_gates[2] = e2 / s; g_gates[3] = e3 / s;
    }
}

__global__ void bias_kernel(const float* __restrict__ in_proj_w,
                            const float* __restrict__ bh, const float* __restrict__ bv,
                            const float* __restrict__ bd, const float* __restrict__ ba,
                            const float* __restrict__ ph, const float* __restrict__ pv,
                            const float* __restrict__ pd, const float* __restrict__ pa) {
    int blk = blockIdx.x;
    int j = threadIdx.x;
    if (blk < 4) {
        const float* pb = (blk == 0) ? bh : (blk == 1) ? bv : (blk == 2) ? bd : ba;
        float s = 0.f;
        const float* row = in_proj_w + j * DIMV;
        for (int k = 0; k < DIMV; k++) s += row[k] * pb[k];
        g_bc[blk * DIMV + j] = s;
    } else {
        g_outb[j] = g_gates[0]*ph[j] + g_gates[1]*pv[j] + g_gates[2]*pd[j] + g_gates[3]*pa[j];
    }
}

// ---------------- 128x128x8 fp32 tile GEMM core ----------------
#define BMT 128
#define BNT 128
#define BKT 8

#define GEMM_COMPUTE(As, Bs, acc, tx, ty)                                     \
    _Pragma("unroll")                                                         \
    for (int kk = 0; kk < BKT; kk++) {                                        \
        float ar[8], br[8];                                                   \
        *(float4*)(ar)     = *(const float4*)&As[kk][(ty) * 8];               \
        *(float4*)(ar + 4) = *(const float4*)&As[kk][(ty) * 8 + 4];           \
        *(float4*)(br)     = *(const float4*)&Bs[kk][(tx) * 8];               \
        *(float4*)(br + 4) = *(const float4*)&Bs[kk][(tx) * 8 + 4];           \
        _Pragma("unroll")                                                     \
        for (int ii = 0; ii < 8; ii++)                                        \
            _Pragma("unroll")                                                 \
            for (int jj = 0; jj < 8; jj++) acc[ii][jj] += ar[ii] * br[jj];    \
    }

// Weight fusion: C = scale * A(512x512, row-major) @ B(512x512, row-major)
// dst_sel 0 -> g_Wc, 1 -> g_Wo
__global__ __launch_bounds__(256) void fuse_gemm(const float* __restrict__ A,
                                                 const float* __restrict__ B,
                                                 int dst_sel, int g, int use_gate) {
    __shared__ float As[BKT][BMT];
    __shared__ float Bs[BKT][BNT];
    int tid = threadIdx.x;
    int n0 = blockIdx.x * BNT, m0 = blockIdx.y * BMT;
    int tx = tid & 15, ty = tid >> 4;
    int lr = tid >> 1, lk4 = (tid & 1) * 4;    // A-tile: 128 rows x 8k
    int bk = tid >> 5, bc4 = (tid & 31) * 4;   // B-tile: 8k x 128 cols
    float acc[8][8] = {};
    const float* Arow = A + (m0 + lr) * DIMV + lk4;

    float4 av = *(const float4*)(Arow);
    float4 bv = *(const float4*)(B + bk * DIMV + n0 + bc4);
    for (int k0 = 0; k0 < DIMV; k0 += BKT) {
        As[lk4 + 0][lr] = av.x; As[lk4 + 1][lr] = av.y;
        As[lk4 + 2][lr] = av.z; As[lk4 + 3][lr] = av.w;
        *(float4*)&Bs[bk][bc4] = bv;
        __syncthreads();
        int k1 = k0 + BKT;
        if (k1 < DIMV) {  // prefetch next tile while computing
            av = *(const float4*)(Arow + k1);
            bv = *(const float4*)(B + (k1 + bk) * DIMV + n0 + bc4);
        }
        GEMM_COMPUTE(As, Bs, acc, tx, ty)
        __syncthreads();
    }
    float s = use_gate ? g_gates[g] : 1.0f;
    float* C = (dst_sel == 0 ? g_Wc : g_Wo) + g * WSZ;
    #pragma unroll
    for (int i = 0; i < 8; i++) {
        float* crow = C + (m0 + ty * 8 + i) * DIMV + n0 + tx * 8;
        #pragma unroll
        for (int j = 0; j < 8; j++) crow[j] = acc[i][j] * s;
    }
}

// Input GEMM (pre-proj + in_proj fused, with sequence gather):
// xz[(g*25088+m), j] = sum_k tokens[gather(m), k] * Wc_g[j,k] + bc_g[j]
__global__ __launch_bounds__(256) void gemm_in(const float* __restrict__ tokens) {
    __shared__ float As[BKT][BMT];
    __shared__ float Bs[BKT][BNT];
    int g = blockIdx.z;
    int tid = threadIdx.x;
    int n0 = blockIdx.x * BNT, m0 = blockIdx.y * BMT;
    int tx = tid & 15, ty = tid >> 4;
    int lr = tid >> 1, lk4 = (tid & 1) * 4;
    int m = m0 + lr;
    int bi = m / NPOS;
    int l = m - bi * NPOS;
    int srcl = l;
    if (g == 1) srcl = (l % 7) * 7 + l / 7;
    else if (g == 2) srcl = c_diag[l];
    else if (g == 3) srcl = c_anti[l];
    const float* Arow = tokens + (size_t)(bi * NPOS + srcl) * DIMV + lk4;
    const float* Bmat = g_Wc + g * WSZ + (n0 + lr) * DIMV + lk4;
    float acc[8][8] = {};

    float4 av = *(const float4*)(Arow);
    float4 bv = *(const float4*)(Bmat);
    for (int k0 = 0; k0 < DIMV; k0 += BKT) {
        As[lk4 + 0][lr] = av.x; As[lk4 + 1][lr] = av.y;
        As[lk4 + 2][lr] = av.z; As[lk4 + 3][lr] = av.w;
        Bs[lk4 + 0][lr] = bv.x; Bs[lk4 + 1][lr] = bv.y;
        Bs[lk4 + 2][lr] = bv.z; Bs[lk4 + 3][lr] = bv.w;
        __syncthreads();
        int k1 = k0 + BKT;
        if (k1 < DIMV) {
            av = *(const float4*)(Arow + k1);
            bv = *(const float4*)(Bmat + k1);
        }
        GEMM_COMPUTE(As, Bs, acc, tx, ty)
        __syncthreads();
    }
    #pragma unroll
    for (int i = 0; i < 8; i++) {
        float* crow = g_xz + ((size_t)(g * TOK_PER_G + m0 + ty * 8 + i)) * DIMV + n0 + tx * 8;
        const float* brow = g_bc + g * DIMV + n0 + tx * 8;
        #pragma unroll
        for (int j = 0; j < 8; j++) crow[j] = acc[i][j] + brow[j];
    }
}

// Output GEMM (out_proj + post-proj + gate sum fused):
// out[m, j] = outb[j] + sum_g sum_k ycat[g*25088+m, k] * Wo_g[j, k]
__global__ __launch_bounds__(256) void gemm_out(float* __restrict__ out) {
    __shared__ float As[BKT][BMT];
    __shared__ float Bs[BKT][BNT];
    int tid = threadIdx.x;
    int n0 = blockIdx.x * BNT, m0 = blockIdx.y * BMT;
    int tx = tid & 15, ty = tid >> 4;
    int lr = tid >> 1, lk4 = (tid & 1) * 4;
    const float* Arow = g_ycat + (size_t)(m0 + lr) * DIMV + lk4;
    const float* Brow = g_Wo + (n0 + lr) * DIMV + lk4;
    float acc[8][8] = {};

    float4 av = *(const float4*)(Arow);
    float4 bv = *(const float4*)(Brow);
    for (int kt = 0; kt < 256; kt++) {
        As[lk4 + 0][lr] = av.x; As[lk4 + 1][lr] = av.y;
        As[lk4 + 2][lr] = av.z; As[lk4 + 3][lr] = av.w;
        Bs[lk4 + 0][lr] = bv.x; Bs[lk4 + 1][lr] = bv.y;
        Bs[lk4 + 2][lr] = bv.z; Bs[lk4 + 3][lr] = bv.w;
        __syncthreads();
        int nt = kt + 1;
        if (nt < 256) {
            int gn = nt >> 6;
            int kn = (nt & 63) * BKT;
            av = *(const float4*)(Arow + (size_t)gn * SLAB + kn);
            bv = *(const float4*)(Brow + (size_t)gn * WSZ + kn);
        }
        GEMM_COMPUTE(As, Bs, acc, tx, ty)
        __syncthreads();
    }
    #pragma unroll
    for (int i = 0; i < 8; i++) {
        float* crow = out + (size_t)(m0 + ty * 8 + i) * DIMV + n0 + tx * 8;
        const float* brow = g_outb + n0 + tx * 8;
        #pragma unroll
        for (int j = 0; j < 8; j++) crow[j] = acc[i][j] + brow[j];
    }
}

// ---------------- fused mamba inner: conv+silu -> x_proj -> LN -> dt_proj -> scan ----------------
// one CTA per batch element (2048), 256 threads (one per half-channel)
__global__ __launch_bounds__(256) void mamba_inner(
    const float* __restrict__ cxw, const float* __restrict__ cxb,
    const float* __restrict__ czw, const float* __restrict__ czb,
    const float* __restrict__ xpw, const float* __restrict__ lnw, const float* __restrict__ lnb,
    const float* __restrict__ dtw, const float* __restrict__ dtb,
    const float* __restrict__ Alog, const float* __restrict__ Dp) {
    extern __shared__ float sm[];
    float* sx   = sm;                 // 256*49 : x channels [d][l]
    float* sz   = sm + 12544;         // 256*49 : z channels [d][l]
    float* sdbl = sm + 25088;         // 49*48  : x_dbl [l][e]
    float* sxp  = sm + 27440;         // 256*48 : x_proj_w transposed [d][e]
    int b = blockIdx.x;
    int t = threadIdx.x;
    const float* base = g_xz + (size_t)b * NPOS * DIMV;

    // load xz (token-major) into channel-major smem
    for (int l = 0; l < NPOS; l++) {
        sx[t * NPOS + l] = base[l * DIMV + t];
        sz[t * NPOS + l] = base[l * DIMV + DHALF + t];
    }
    // transpose x_proj_w into smem [d][e]
    for (int i = t; i < EDIM * DHALF; i += 256) {
        int e = i >> 8, d = i & 255;
        sxp[d * EDIM + e] = xpw[i];
    }
    // depthwise conv k=3 SAME + SiLU, in place (each thread owns its channel row)
    {
        float w0 = cxw[t * 3], w1 = cxw[t * 3 + 1], w2 = cxw[t * 3 + 2], bb = cxb[t];
        float prev = 0.f;
        for (int l = 0; l < NPOS; l++) {
            float cur = sx[t * NPOS + l];
            float nxt = (l < NPOS - 1) ? sx[t * NPOS + l + 1] : 0.f;
            float v = w0 * prev + w1 * cur + w2 * nxt + bb;
            v = v / (1.f + expf(-v));
            prev = cur;
            sx[t * NPOS + l] = v;
        }
        w0 = czw[t * 3]; w1 = czw[t * 3 + 1]; w2 = czw[t * 3 + 2]; bb = czb[t];
        prev = 0.f;
        for (int l = 0; l < NPOS; l++) {
            float cur = sz[t * NPOS + l];
            float nxt = (l < NPOS - 1) ? sz[t * NPOS + l + 1] : 0.f;
            float v = w0 * prev + w1 * cur + w2 * nxt + bb;
            v = v / (1.f + expf(-v));
            prev = cur;
            sz[t * NPOS + l] = v;
        }
    }
    __syncthreads();

    // x_dbl[l][e] = sum_d x_conv[d][l] * xp[e][d]   (49*6 tasks of 8 e's each)
    for (int task = t; task < NPOS * 6; task += 256) {
        int l = task / 6, ec = task % 6;
        float acc[8] = {};
        for (int d = 0; d < DHALF; d++) {
            float xv = sx[d * NPOS + l];
            float4 p0 = *(const float4*)&sxp[d * EDIM + ec * 8];
            float4 p1 = *(const float4*)&sxp[d * EDIM + ec * 8 + 4];
            acc[0] += xv * p0.x; acc[1] += xv * p0.y; acc[2] += xv * p0.z; acc[3] += xv * p0.w;
            acc[4] += xv * p1.x; acc[5] += xv * p1.y; acc[6] += xv * p1.z; acc[7] += xv * p1.w;
        }
        #pragma unroll
        for (int j = 0; j < 8; j++) sdbl[l * EDIM + ec * 8 + j] = acc[j];
    }
    __syncthreads();

    // LayerNorm over E=48 per position (threads 0..48)
    if (t < NPOS) {
        float* row = &sdbl[t * EDIM];
        float m = 0.f;
        for (int e = 0; e < EDIM; e++) m += row[e];
        m *= (1.f / EDIM);
        float v = 0.f;
        for (int e = 0; e < EDIM; e++) { float d = row[e] - m; v += d * d; }
        v *= (1.f / EDIM);
        float rs = rsqrtf(v + 1e-5f);
        for (int e = 0; e < EDIM; e++) row[e] = (row[e] - m) * rs * lnw[e] + lnb[e];
    }
    __syncthreads();

    // selective scan: thread t = channel d
    float wreg[32];
    #pragma unroll
    for (int r = 0; r < 32; r += 4)
        *(float4*)&wreg[r] = *(const float4*)&dtw[t * 32 + r];
    float a[8];
    #pragma unroll
    for (int n = 0; n < 8; n++) a[n] = -expf(Alog[t * 8 + n]);
    float Dv = Dp[t], bias = dtb[t];
    float h[8] = {};
    float* yout = g_ycat + (size_t)b * NPOS * DIMV;
    for (int l = 0; l < NPOS; l++) {
        const float* rowp = &sdbl[l * EDIM];
        float u = sx[t * NPOS + l];
        float s = bias;
        #pragma unroll
        for (int r = 0; r < 32; r += 4) {
            float4 x4 = *(const float4*)&rowp[r];
            s += wreg[r] * x4.x + wreg[r + 1] * x4.y + wreg[r + 2] * x4.z + wreg[r + 3] * x4.w;
        }
        float dt = (s > 20.f) ? s : log1pf(expf(s));
        float y = 0.f;
        #pragma unroll
        for (int n = 0; n < 8; n++) {
            float Bn = rowp[32 + n], Cn = rowp[40 + n];
            h[n] = h[n] * expf(dt * a[n]) + dt * Bn * u;
            y += h[n] * Cn;
        }
        y += Dv * u;
        if (isnan(y)) y = 0.f;
        else if (isinf(y)) y = (y > 0.f) ? 3.402823466e38f : -3.402823466e38f;
        yout[l * DIMV + t] = y;
    }
    for (int l = 0; l < NPOS; l++) yout[l * DIMV + DHALF + t] = sz[t * NPOS + l];
}

// ---------------- host launcher ----------------
extern "C" void kernel_launch(void* const* d_in, const int* in_sizes, int n_in,
                              void* d_out, int out_size) {
    // Input order disambiguation:
    //   signature order: d_in[10] = conv_x_w (768 elems)
    //   setup_inputs dict order: d_in[10] = post_h_b (512 elems)
    int dict_order = (in_sizes[10] != 768);

    const float* tokens = (const float*)d_in[0];
    const float* pre_w[4], *pre_b[4], *post_w[4], *post_b[4];
    const float *in_proj_w, *conv_x_w, *conv_x_b, *conv_z_w, *conv_z_b;
    const float *x_proj_w, *ln_w, *ln_b, *dt_proj_w, *dt_proj_b;
    const float *A_log, *D_param, *out_proj_w, *gate_logits;

    for (int g = 0; g < 4; g++) {
        pre_w[g] = (const float*)d_in[1 + 2 * g];
        pre_b[g] = (const float*)d_in[2 + 2 * g];
    }
    if (dict_order) {
        for (int g = 0; g < 4; g++) {
            post_w[g] = (const float*)d_in[9 + 2 * g];
            post_b[g] = (const float*)d_in[10 + 2 * g];
        }
        in_proj_w  = (const float*)d_in[17];
        conv_x_w   = (const float*)d_in[18];
        conv_x_b   = (const float*)d_in[19];
        conv_z_w   = (const float*)d_in[20];
        conv_z_b   = (const float*)d_in[21];
        x_proj_w   = (const float*)d_in[22];
        ln_w       = (const float*)d_in[23];
        ln_b       = (const float*)d_in[24];
        dt_proj_w  = (const float*)d_in[25];
        dt_proj_b  = (const float*)d_in[26];
        A_log      = (const float*)d_in[27];
        D_param    = (const float*)d_in[28];
        out_proj_w = (const float*)d_in[29];
        gate_logits = (const float*)d_in[30];
    } else {
        in_proj_w  = (const float*)d_in[9];
        conv_x_w   = (const float*)d_in[10];
        conv_x_b   = (const float*)d_in[11];
        conv_z_w   = (const float*)d_in[12];
        conv_z_b   = (const float*)d_in[13];
        x_proj_w   = (const float*)d_in[14];
        ln_w       = (const float*)d_in[15];
        ln_b       = (const float*)d_in[16];
        dt_proj_w  = (const float*)d_in[17];
        dt_proj_b  = (const float*)d_in[18];
        A_log      = (const float*)d_in[19];
        D_param    = (const float*)d_in[20];
        out_proj_w = (const float*)d_in[21];
        for (int g = 0; g < 4; g++) {
            post_w[g] = (const float*)d_in[22 + 2 * g];
            post_b[g] = (const float*)d_in[23 + 2 * g];
        }
        gate_logits = (const float*)d_in[30];
    }
    float* out = (float*)d_out;

    const int SMEM_INNER = (12544 * 2 + 2352 + 12288) * 4;  // 158,912 B
    cudaFuncSetAttribute(mamba_inner, cudaFuncAttributeMaxDynamicSharedMemorySize, SMEM_INNER);

    gates_kernel<<<1, 32>>>(gate_logits);
    bias_kernel<<<5, 512>>>(in_proj_w, pre_b[0], pre_b[1], pre_b[2], pre_b[3],
                            post_b[0], post_b[1], post_b[2], post_b[3]);

    dim3 g44(4, 4);
    for (int g = 0; g < 4; g++)
        fuse_gemm<<<g44, 256>>>(in_proj_w, pre_w[g], 0, g, 0);     // Wc_g = in_proj @ pre_g
    for (int g = 0; g < 4; g++)
        fuse_gemm<<<g44, 256>>>(post_w[g], out_proj_w, 1, g, 1);   // Wo_g = gate_g * post_g @ out_proj

    gemm_in<<<dim3(4, 196, 4), 256>>>(tokens);
    mamba_inner<<<2048, 256, SMEM_INNER>>>(conv_x_w, conv_x_b, conv_z_w, conv_z_b,
                                           x_proj_w, ln_w, ln_b, dt_proj_w, dt_proj_b,
                                           A_log, D_param);
    gemm_out<<<dim3(4, 196), 256>>>(out);
    (void)n_in; (void)out_size;
}

// round 6
// speedup vs baseline: 1.1359x; 1.1359x over previous
#include <cuda_runtime.h>
#include <cuda_bf16.h>
#include <math.h>
#include <stdint.h>

#define NPOS 49
#define DIMV 512
#define DHALF 256
#define EDIM 48
#define TOK_PER_G 25088            // 512*49
#define SLAB 12845056              // 25088*512 (elements)
#define WSZ 262144                 // 512*512

// ---------------- device scratch (no allocations allowed) ----------------
__device__ float g_xz[51380224];                         // (2048, 49, 512) fp32
__device__ __align__(16) __nv_bfloat16 g_tok_h[12845056];
__device__ __align__(16) __nv_bfloat16 g_tok_l[12845056];
__device__ __align__(16) __nv_bfloat16 g_yc_h[51380224];
__device__ __align__(16) __nv_bfloat16 g_yc_l[51380224];
__device__ __align__(16) __nv_bfloat16 g_Wc_h[4 * WSZ];
__device__ __align__(16) __nv_bfloat16 g_Wc_l[4 * WSZ];
__device__ __align__(16) __nv_bfloat16 g_Wo_h[4 * WSZ];
__device__ __align__(16) __nv_bfloat16 g_Wo_l[4 * WSZ];
__device__ float g_bc[4 * DIMV];
__device__ float g_outb[DIMV];
__device__ float g_gates[4];

__constant__ int c_diag[49] = {0,1,7,2,8,14,3,9,15,21,4,10,16,22,28,5,11,17,23,29,35,
                               6,12,18,24,30,36,42,13,19,25,31,37,43,20,26,32,38,44,
                               27,33,39,45,34,40,46,41,47,48};
__constant__ int c_anti[49] = {6,5,13,4,12,20,3,11,19,27,2,10,18,26,34,1,9,17,25,33,41,
                               0,8,16,24,32,40,48,7,15,23,31,39,47,14,22,30,38,46,
                               21,29,37,45,28,36,44,35,43,42};

// ---------------- mma.sync helpers (baseline PTX, valid on sm_103) ----------------
__device__ __forceinline__ uint32_t smem_u32(const void* p) {
    uint32_t a;
    asm("{ .reg .u64 t; cvta.to.shared.u64 t, %1; cvt.u32.u64 %0, t; }" : "=r"(a) : "l"(p));
    return a;
}
__device__ __forceinline__ void ldsm_x4(uint32_t* r, uint32_t addr) {
    asm volatile("ldmatrix.sync.aligned.m8n8.x4.shared.b16 {%0,%1,%2,%3}, [%4];"
                 : "=r"(r[0]), "=r"(r[1]), "=r"(r[2]), "=r"(r[3]) : "r"(addr));
}
__device__ __forceinline__ void mma16816(float* c, const uint32_t* a, const uint32_t* b) {
    asm volatile(
        "mma.sync.aligned.m16n8k16.row.col.f32.bf16.bf16.f32 "
        "{%0,%1,%2,%3}, {%4,%5,%6,%7}, {%8,%9}, {%0,%1,%2,%3};"
        : "+f"(c[0]), "+f"(c[1]), "+f"(c[2]), "+f"(c[3])
        : "r"(a[0]), "r"(a[1]), "r"(a[2]), "r"(a[3]), "r"(b[0]), "r"(b[1]));
}

// smem layout per stage (bytes): Ah 0, Al 10240, Bh 20480, Bl 30720; stage stride 40960
#define ST_STRIDE 40960
#define SMEM_MMA 81920
#define ROWB 80            // bytes per padded row (40 halves)

// ---------------- small prep kernels ----------------
__global__ void gates_kernel(const float* __restrict__ gl) {
    if (threadIdx.x == 0) {
        float m = fmaxf(fmaxf(gl[0], gl[1]), fmaxf(gl[2], gl[3]));
        float e0 = expf(gl[0] - m), e1 = expf(gl[1] - m), e2 = expf(gl[2] - m), e3 = expf(gl[3] - m);
        float s = e0 + e1 + e2 + e3;
        g_gates[0] = e0 / s; g_gates[1] = e1 / s; g_gates[2] = e2 / s; g_gates[3] = e3 / s;
    }
}

__global__ void bias_kernel(const float* __restrict__ in_proj_w,
                            const float* __restrict__ bh, const float* __restrict__ bv,
                            const float* __restrict__ bd, const float* __restrict__ ba,
                            const float* __restrict__ ph, const float* __restrict__ pv,
                            const float* __restrict__ pd, const float* __restrict__ pa) {
    int blk = blockIdx.x;
    int j = threadIdx.x;
    if (blk < 4) {
        const float* pb = (blk == 0) ? bh : (blk == 1) ? bv : (blk == 2) ? bd : ba;
        float s = 0.f;
        const float* row = in_proj_w + j * DIMV;
        for (int k = 0; k < DIMV; k++) s += row[k] * pb[k];
        g_bc[blk * DIMV + j] = s;
    } else {
        g_outb[j] = g_gates[0]*ph[j] + g_gates[1]*pv[j] + g_gates[2]*pd[j] + g_gates[3]*pa[j];
    }
}

// tokens fp32 -> bf16 hi/lo
__global__ __launch_bounds__(256) void tok_split(const float* __restrict__ tk) {
    size_t i = ((size_t)blockIdx.x * 256 + threadIdx.x) * 4;
    float4 v = *(const float4*)(tk + i);
    __nv_bfloat16 h0 = __float2bfloat16(v.x), h1 = __float2bfloat16(v.y);
    __nv_bfloat16 h2 = __float2bfloat16(v.z), h3 = __float2bfloat16(v.w);
    __nv_bfloat16 l0 = __float2bfloat16(v.x - __bfloat162float(h0));
    __nv_bfloat16 l1 = __float2bfloat16(v.y - __bfloat162float(h1));
    __nv_bfloat16 l2 = __float2bfloat16(v.z - __bfloat162float(h2));
    __nv_bfloat16 l3 = __float2bfloat16(v.w - __bfloat162float(h3));
    *(__nv_bfloat162*)(g_tok_h + i)     = __nv_bfloat162(h0, h1);
    *(__nv_bfloat162*)(g_tok_h + i + 2) = __nv_bfloat162(h2, h3);
    *(__nv_bfloat162*)(g_tok_l + i)     = __nv_bfloat162(l0, l1);
    *(__nv_bfloat162*)(g_tok_l + i + 2) = __nv_bfloat162(l2, l3);
}

// ---------------- batched weight-fusion GEMM (8 products, one launch) ----------------
#define BKT 8
#define GEMM_COMPUTE(As, Bs, acc, tx, ty)                                     \
    _Pragma("unroll")                                                         \
    for (int kk = 0; kk < BKT; kk++) {                                        \
        float ar[8], br[8];                                                   \
        *(float4*)(ar)     = *(const float4*)&As[kk][(ty) * 8];               \
        *(float4*)(ar + 4) = *(const float4*)&As[kk][(ty) * 8 + 4];           \
        *(float4*)(br)     = *(const float4*)&Bs[kk][(tx) * 8];               \
        *(float4*)(br + 4) = *(const float4*)&Bs[kk][(tx) * 8 + 4];           \
        _Pragma("unroll")                                                     \
        for (int ii = 0; ii < 8; ii++)                                        \
            _Pragma("unroll")                                                 \
            for (int jj = 0; jj < 8; jj++) acc[ii][jj] += ar[ii] * br[jj];    \
    }

__global__ __launch_bounds__(256) void fuse_gemm_all(
    const float* __restrict__ in_proj, const float* __restrict__ p0,
    const float* __restrict__ p1, const float* __restrict__ p2, const float* __restrict__ p3,
    const float* __restrict__ outp, const float* __restrict__ q0,
    const float* __restrict__ q1, const float* __restrict__ q2, const float* __restrict__ q3) {
    __shared__ float As[BKT][128];
    __shared__ float Bs[BKT][128];
    int z = blockIdx.z;
    const float* A; const float* B;
    __nv_bfloat16 *Ch, *Cl; float scale;
    if (z < 4) {
        A = in_proj;
        B = (z == 0) ? p0 : (z == 1) ? p1 : (z == 2) ? p2 : p3;
        Ch = g_Wc_h + z * WSZ; Cl = g_Wc_l + z * WSZ; scale = 1.f;
    } else {
        int g = z - 4;
        A = (g == 0) ? q0 : (g == 1) ? q1 : (g == 2) ? q2 : q3;
        B = outp;
        Ch = g_Wo_h + g * WSZ; Cl = g_Wo_l + g * WSZ; scale = g_gates[g];
    }
    int tid = threadIdx.x;
    int n0 = blockIdx.x * 128, m0 = blockIdx.y * 128;
    int tx = tid & 15, ty = tid >> 4;
    int lr = tid >> 1, lk4 = (tid & 1) * 4;
    int bk = tid >> 5, bc4 = (tid & 31) * 4;
    float acc[8][8] = {};
    const float* Arow = A + (m0 + lr) * DIMV + lk4;

    float4 av = *(const float4*)(Arow);
    float4 bv = *(const float4*)(B + bk * DIMV + n0 + bc4);
    for (int k0 = 0; k0 < DIMV; k0 += BKT) {
        As[lk4 + 0][lr] = av.x; As[lk4 + 1][lr] = av.y;
        As[lk4 + 2][lr] = av.z; As[lk4 + 3][lr] = av.w;
        *(float4*)&Bs[bk][bc4] = bv;
        __syncthreads();
        int k1 = k0 + BKT;
        if (k1 < DIMV) {
            av = *(const float4*)(Arow + k1);
            bv = *(const float4*)(B + (k1 + bk) * DIMV + n0 + bc4);
        }
        GEMM_COMPUTE(As, Bs, acc, tx, ty)
        __syncthreads();
    }
    #pragma unroll
    for (int i = 0; i < 8; i++) {
        int row = m0 + ty * 8 + i;
        #pragma unroll
        for (int j = 0; j < 8; j++) {
            float v = acc[i][j] * scale;
            __nv_bfloat16 h = __float2bfloat16(v);
            __nv_bfloat16 l = __float2bfloat16(v - __bfloat162float(h));
            Ch[row * DIMV + n0 + tx * 8 + j] = h;
            Cl[row * DIMV + n0 + tx * 8 + j] = l;
        }
    }
}

// ---------------- HMMA split-bf16 core (shared by both big GEMMs) ----------------
// compute one 128x128x32 chunk from stage smem into acc
__device__ __forceinline__ void mma_chunk(uint32_t sbase, float acc[2][8][4],
                                          int wm, int wn, int l) {
    #pragma unroll
    for (int ks = 0; ks < 2; ks++) {
        uint32_t ah[2][4], al[2][4], bh[4][4], bl[4][4];
        int ko = ks * 32;  // bytes (16 halves)
        #pragma unroll
        for (int mt = 0; mt < 2; mt++) {
            int row = wm * 32 + mt * 16 + (l & 15);
            uint32_t ad = sbase + row * ROWB + ko + ((l >> 4) * 16);
            ldsm_x4(ah[mt], ad);
            ldsm_x4(al[mt], ad + 10240);
        }
        #pragma unroll
        for (int np = 0; np < 4; np++) {
            int nrow = wn * 64 + np * 16 + (l & 7) + ((l >> 4) << 3);
            uint32_t bd = sbase + 20480 + nrow * ROWB + ko + (((l >> 3) & 1) * 16);
            ldsm_x4(bh[np], bd);
            ldsm_x4(bl[np], bd + 10240);
        }
        #pragma unroll
        for (int mt = 0; mt < 2; mt++)
            #pragma unroll
            for (int nt = 0; nt < 8; nt++) {
                mma16816(acc[mt][nt], ah[mt], &bh[nt >> 1][(nt & 1) * 2]);
                mma16816(acc[mt][nt], ah[mt], &bl[nt >> 1][(nt & 1) * 2]);
                mma16816(acc[mt][nt], al[mt], &bh[nt >> 1][(nt & 1) * 2]);
            }
    }
}

#define STORE_STAGE(stp)                                                      \
    do {                                                                      \
        __nv_bfloat16* st = (__nv_bfloat16*)(smem + (stp) * ST_STRIDE);       \
        *(float4*)(st + sOff0)         = pf[0];                               \
        *(float4*)(st + sOff1)         = pf[1];                               \
        *(float4*)(st + 5120 + sOff0)  = pf[2];                               \
        *(float4*)(st + 5120 + sOff1)  = pf[3];                               \
        *(float4*)(st + 10240 + sOff0) = pf[4];                               \
        *(float4*)(st + 10240 + sOff1) = pf[5];                               \
        *(float4*)(st + 15360 + sOff0) = pf[6];                               \
        *(float4*)(st + 15360 + sOff1) = pf[7];                               \
    } while (0)

// Input GEMM: xz[g*25088+m, n] = sum_k tok[gather(m), k] * Wc_g[n, k] + bc_g[n]
__global__ __launch_bounds__(256) void gemm_in_mma() {
    extern __shared__ char smem[];
    const int t = threadIdx.x;
    const int w = t >> 5, l = t & 31;
    const int wm = w & 3, wn = w >> 2;
    const int n0 = blockIdx.x * 128, m0 = blockIdx.y * 128, g = blockIdx.z;

    const int lr0 = t >> 2;
    const int seg = (t & 3) * 8;     // halves
    size_t aG[2], bG[2];
    #pragma unroll
    for (int p = 0; p < 2; p++) {
        int r = lr0 + p * 64;
        int m = m0 + r;
        int bi = m / NPOS, ll = m - bi * NPOS;
        int srcl = ll;
        if (g == 1) srcl = (ll % 7) * 7 + ll / 7;
        else if (g == 2) srcl = c_diag[ll];
        else if (g == 3) srcl = c_anti[ll];
        aG[p] = (size_t)(bi * NPOS + srcl) * DIMV + seg;
        bG[p] = (size_t)g * WSZ + (size_t)(n0 + r) * DIMV + seg;
    }
    const int sOff0 = lr0 * 40 + seg;
    const int sOff1 = (lr0 + 64) * 40 + seg;
    const uint32_t sb32 = smem_u32(smem);

    float acc[2][8][4];
    #pragma unroll
    for (int i = 0; i < 2; i++)
        #pragma unroll
        for (int j = 0; j < 8; j++)
            #pragma unroll
            for (int q = 0; q < 4; q++) acc[i][j][q] = 0.f;

    float4 pf[8];
    pf[0] = *(const float4*)(g_tok_h + aG[0]); pf[1] = *(const float4*)(g_tok_h + aG[1]);
    pf[2] = *(const float4*)(g_tok_l + aG[0]); pf[3] = *(const float4*)(g_tok_l + aG[1]);
    pf[4] = *(const float4*)(g_Wc_h + bG[0]);  pf[5] = *(const float4*)(g_Wc_h + bG[1]);
    pf[6] = *(const float4*)(g_Wc_l + bG[0]);  pf[7] = *(const float4*)(g_Wc_l + bG[1]);
    STORE_STAGE(0);
    __syncthreads();

    for (int c = 0; c < 16; c++) {
        int s = c & 1;
        if (c + 1 < 16) {
            int kc = (c + 1) * 32;
            pf[0] = *(const float4*)(g_tok_h + aG[0] + kc); pf[1] = *(const float4*)(g_tok_h + aG[1] + kc);
            pf[2] = *(const float4*)(g_tok_l + aG[0] + kc); pf[3] = *(const float4*)(g_tok_l + aG[1] + kc);
            pf[4] = *(const float4*)(g_Wc_h + bG[0] + kc);  pf[5] = *(const float4*)(g_Wc_h + bG[1] + kc);
            pf[6] = *(const float4*)(g_Wc_l + bG[0] + kc);  pf[7] = *(const float4*)(g_Wc_l + bG[1] + kc);
        }
        mma_chunk(sb32 + s * ST_STRIDE, acc, wm, wn, l);
        __syncthreads();
        if (c + 1 < 16) {
            STORE_STAGE((c + 1) & 1);
            __syncthreads();
        }
    }

    int lrow = l >> 2, lcol = (l & 3) * 2;
    #pragma unroll
    for (int mt = 0; mt < 2; mt++) {
        int m = m0 + wm * 32 + mt * 16 + lrow;
        float* dbase = g_xz + (size_t)(g * TOK_PER_G + m) * DIMV;
        #pragma unroll
        for (int nt = 0; nt < 8; nt++) {
            int n = n0 + wn * 64 + nt * 8 + lcol;
            float b0 = g_bc[g * DIMV + n], b1 = g_bc[g * DIMV + n + 1];
            dbase[n]              = acc[mt][nt][0] + b0;
            dbase[n + 1]          = acc[mt][nt][1] + b1;
            dbase[8 * DIMV + n]     = acc[mt][nt][2] + b0;
            dbase[8 * DIMV + n + 1] = acc[mt][nt][3] + b1;
        }
    }
}

// Output GEMM: out[m, n] = outb[n] + sum_g sum_k ycat[g*25088+m, k] * Wo_g[n, k]
__global__ __launch_bounds__(256) void gemm_out_mma(float* __restrict__ out) {
    extern __shared__ char smem[];
    const int t = threadIdx.x;
    const int w = t >> 5, l = t & 31;
    const int wm = w & 3, wn = w >> 2;
    const int n0 = blockIdx.x * 128, m0 = blockIdx.y * 128;

    const int lr0 = t >> 2;
    const int seg = (t & 3) * 8;
    size_t aG[2], bG[2];
    #pragma unroll
    for (int p = 0; p < 2; p++) {
        int r = lr0 + p * 64;
        aG[p] = (size_t)(m0 + r) * DIMV + seg;
        bG[p] = (size_t)(n0 + r) * DIMV + seg;
    }
    const int sOff0 = lr0 * 40 + seg;
    const int sOff1 = (lr0 + 64) * 40 + seg;
    const uint32_t sb32 = smem_u32(smem);

    float acc[2][8][4];
    #pragma unroll
    for (int i = 0; i < 2; i++)
        #pragma unroll
        for (int j = 0; j < 8; j++)
            #pragma unroll
            for (int q = 0; q < 4; q++) acc[i][j][q] = 0.f;

    float4 pf[8];
    pf[0] = *(const float4*)(g_yc_h + aG[0]); pf[1] = *(const float4*)(g_yc_h + aG[1]);
    pf[2] = *(const float4*)(g_yc_l + aG[0]); pf[3] = *(const float4*)(g_yc_l + aG[1]);
    pf[4] = *(const float4*)(g_Wo_h + bG[0]); pf[5] = *(const float4*)(g_Wo_h + bG[1]);
    pf[6] = *(const float4*)(g_Wo_l + bG[0]); pf[7] = *(const float4*)(g_Wo_l + bG[1]);
    STORE_STAGE(0);
    __syncthreads();

    for (int c = 0; c < 64; c++) {
        int s = c & 1;
        if (c + 1 < 64) {
            int cn = c + 1;
            size_t aS = (size_t)(cn >> 4) * SLAB + (size_t)(cn & 15) * 32;
            size_t bS = (size_t)(cn >> 4) * WSZ + (size_t)(cn & 15) * 32;
            pf[0] = *(const float4*)(g_yc_h + aS + aG[0]); pf[1] = *(const float4*)(g_yc_h + aS + aG[1]);
            pf[2] = *(const float4*)(g_yc_l + aS + aG[0]); pf[3] = *(const float4*)(g_yc_l + aS + aG[1]);
            pf[4] = *(const float4*)(g_Wo_h + bS + bG[0]); pf[5] = *(const float4*)(g_Wo_h + bS + bG[1]);
            pf[6] = *(const float4*)(g_Wo_l + bS + bG[0]); pf[7] = *(const float4*)(g_Wo_l + bS + bG[1]);
        }
        mma_chunk(sb32 + s * ST_STRIDE, acc, wm, wn, l);
        __syncthreads();
        if (c + 1 < 64) {
            STORE_STAGE((c + 1) & 1);
            __syncthreads();
        }
    }

    int lrow = l >> 2, lcol = (l & 3) * 2;
    #pragma unroll
    for (int mt = 0; mt < 2; mt++) {
        int m = m0 + wm * 32 + mt * 16 + lrow;
        float* dbase = out + (size_t)m * DIMV;
        #pragma unroll
        for (int nt = 0; nt < 8; nt++) {
            int n = n0 + wn * 64 + nt * 8 + lcol;
            float b0 = g_outb[n], b1 = g_outb[n + 1];
            dbase[n]              = acc[mt][nt][0] + b0;
            dbase[n + 1]          = acc[mt][nt][1] + b1;
            dbase[8 * DIMV + n]     = acc[mt][nt][2] + b0;
            dbase[8 * DIMV + n + 1] = acc[mt][nt][3] + b1;
        }
    }
}

// ---------------- fused mamba inner: conv+silu -> x_proj -> LN -> dt_proj -> scan ----------------
__global__ __launch_bounds__(256) void mamba_inner(
    const float* __restrict__ cxw, const float* __restrict__ cxb,
    const float* __restrict__ czw, const float* __restrict__ czb,
    const float* __restrict__ xpw, const float* __restrict__ lnw, const float* __restrict__ lnb,
    const float* __restrict__ dtw, const float* __restrict__ dtb,
    const float* __restrict__ Alog, const float* __restrict__ Dp) {
    extern __shared__ float sm[];
    float* sx   = sm;                 // 256*49
    float* sz   = sm + 12544;         // 256*49
    float* sdbl = sm + 25088;         // 49*48
    float* sxp  = sm + 27440;         // 256*48
    int b = blockIdx.x;
    int t = threadIdx.x;
    const float* base = g_xz + (size_t)b * NPOS * DIMV;

    for (int l = 0; l < NPOS; l++) {
        sx[t * NPOS + l] = base[l * DIMV + t];
        sz[t * NPOS + l] = base[l * DIMV + DHALF + t];
    }
    for (int i = t; i < EDIM * DHALF; i += 256) {
        int e = i >> 8, d = i & 255;
        sxp[d * EDIM + e] = xpw[i];
    }
    {
        float w0 = cxw[t * 3], w1 = cxw[t * 3 + 1], w2 = cxw[t * 3 + 2], bb = cxb[t];
        float prev = 0.f;
        for (int l = 0; l < NPOS; l++) {
            float cur = sx[t * NPOS + l];
            float nxt = (l < NPOS - 1) ? sx[t * NPOS + l + 1] : 0.f;
            float v = w0 * prev + w1 * cur + w2 * nxt + bb;
            v = v / (1.f + expf(-v));
            prev = cur;
            sx[t * NPOS + l] = v;
        }
        w0 = czw[t * 3]; w1 = czw[t * 3 + 1]; w2 = czw[t * 3 + 2]; bb = czb[t];
        prev = 0.f;
        for (int l = 0; l < NPOS; l++) {
            float cur = sz[t * NPOS + l];
            float nxt = (l < NPOS - 1) ? sz[t * NPOS + l + 1] : 0.f;
            float v = w0 * prev + w1 * cur + w2 * nxt + bb;
            v = v / (1.f + expf(-v));
            prev = cur;
            sz[t * NPOS + l] = v;
        }
    }
    __syncthreads();

    for (int task = t; task < NPOS * 6; task += 256) {
        int l = task / 6, ec = task % 6;
        float acc[8] = {};
        for (int d = 0; d < DHALF; d++) {
            float xv = sx[d * NPOS + l];
            float4 p0 = *(const float4*)&sxp[d * EDIM + ec * 8];
            float4 p1 = *(const float4*)&sxp[d * EDIM + ec * 8 + 4];
            acc[0] += xv * p0.x; acc[1] += xv * p0.y; acc[2] += xv * p0.z; acc[3] += xv * p0.w;
            acc[4] += xv * p1.x; acc[5] += xv * p1.y; acc[6] += xv * p1.z; acc[7] += xv * p1.w;
        }
        #pragma unroll
        for (int j = 0; j < 8; j++) sdbl[l * EDIM + ec * 8 + j] = acc[j];
    }
    __syncthreads();

    if (t < NPOS) {
        float* row = &sdbl[t * EDIM];
        float m = 0.f;
        for (int e = 0; e < EDIM; e++) m += row[e];
        m *= (1.f / EDIM);
        float v = 0.f;
        for (int e = 0; e < EDIM; e++) { float d = row[e] - m; v += d * d; }
        v *= (1.f / EDIM);
        float rs = rsqrtf(v + 1e-5f);
        for (int e = 0; e < EDIM; e++) row[e] = (row[e] - m) * rs * lnw[e] + lnb[e];
    }
    __syncthreads();

    float wreg[32];
    #pragma unroll
    for (int r = 0; r < 32; r += 4)
        *(float4*)&wreg[r] = *(const float4*)&dtw[t * 32 + r];
    float a[8];
    #pragma unroll
    for (int n = 0; n < 8; n++) a[n] = -expf(Alog[t * 8 + n]);
    float Dv = Dp[t], bias = dtb[t];
    float h[8] = {};
    size_t ybase = (size_t)b * NPOS * DIMV;
    for (int l = 0; l < NPOS; l++) {
        const float* rowp = &sdbl[l * EDIM];
        float u = sx[t * NPOS + l];
        float s = bias;
        #pragma unroll
        for (int r = 0; r < 32; r += 4) {
            float4 x4 = *(const float4*)&rowp[r];
            s += wreg[r] * x4.x + wreg[r + 1] * x4.y + wreg[r + 2] * x4.z + wreg[r + 3] * x4.w;
        }
        float dt = (s > 20.f) ? s : log1pf(expf(s));
        float y = 0.f;
        #pragma unroll
        for (int n = 0; n < 8; n++) {
            float Bn = rowp[32 + n], Cn = rowp[40 + n];
            h[n] = h[n] * expf(dt * a[n]) + dt * Bn * u;
            y += h[n] * Cn;
        }
        y += Dv * u;
        if (isnan(y)) y = 0.f;
        else if (isinf(y)) y = (y > 0.f) ? 3.402823466e38f : -3.402823466e38f;
        size_t idx = ybase + (size_t)l * DIMV + t;
        __nv_bfloat16 hy = __float2bfloat16(y);
        g_yc_h[idx] = hy;
        g_yc_l[idx] = __float2bfloat16(y - __bfloat162float(hy));
    }
    for (int l = 0; l < NPOS; l++) {
        float zz = sz[t * NPOS + l];
        size_t idx = ybase + (size_t)l * DIMV + DHALF + t;
        __nv_bfloat16 hz = __float2bfloat16(zz);
        g_yc_h[idx] = hz;
        g_yc_l[idx] = __float2bfloat16(zz - __bfloat162float(hz));
    }
}

// ---------------- host launcher ----------------
extern "C" void kernel_launch(void* const* d_in, const int* in_sizes, int n_in,
                              void* d_out, int out_size) {
    int dict_order = (in_sizes[10] != 768);

    const float* tokens = (const float*)d_in[0];
    const float* pre_w[4], *pre_b[4], *post_w[4], *post_b[4];
    const float *in_proj_w, *conv_x_w, *conv_x_b, *conv_z_w, *conv_z_b;
    const float *x_proj_w, *ln_w, *ln_b, *dt_proj_w, *dt_proj_b;
    const float *A_log, *D_param, *out_proj_w, *gate_logits;

    for (int g = 0; g < 4; g++) {
        pre_w[g] = (const float*)d_in[1 + 2 * g];
        pre_b[g] = (const float*)d_in[2 + 2 * g];
    }
    if (dict_order) {
        for (int g = 0; g < 4; g++) {
            post_w[g] = (const float*)d_in[9 + 2 * g];
            post_b[g] = (const float*)d_in[10 + 2 * g];
        }
        in_proj_w  = (const float*)d_in[17];
        conv_x_w   = (const float*)d_in[18];
        conv_x_b   = (const float*)d_in[19];
        conv_z_w   = (const float*)d_in[20];
        conv_z_b   = (const float*)d_in[21];
        x_proj_w   = (const float*)d_in[22];
        ln_w       = (const float*)d_in[23];
        ln_b       = (const float*)d_in[24];
        dt_proj_w  = (const float*)d_in[25];
        dt_proj_b  = (const float*)d_in[26];
        A_log      = (const float*)d_in[27];
        D_param    = (const float*)d_in[28];
        out_proj_w = (const float*)d_in[29];
        gate_logits = (const float*)d_in[30];
    } else {
        in_proj_w  = (const float*)d_in[9];
        conv_x_w   = (const float*)d_in[10];
        conv_x_b   = (const float*)d_in[11];
        conv_z_w   = (const float*)d_in[12];
        conv_z_b   = (const float*)d_in[13];
        x_proj_w   = (const float*)d_in[14];
        ln_w       = (const float*)d_in[15];
        ln_b       = (const float*)d_in[16];
        dt_proj_w  = (const float*)d_in[17];
        dt_proj_b  = (const float*)d_in[18];
        A_log      = (const float*)d_in[19];
        D_param    = (const float*)d_in[20];
        out_proj_w = (const float*)d_in[21];
        for (int g = 0; g < 4; g++) {
            post_w[g] = (const float*)d_in[22 + 2 * g];
            post_b[g] = (const float*)d_in[23 + 2 * g];
        }
        gate_logits = (const float*)d_in[30];
    }
    float* out = (float*)d_out;

    const int SMEM_INNER = (12544 * 2 + 2352 + 12288) * 4;  // 158,912 B
    cudaFuncSetAttribute(mamba_inner, cudaFuncAttributeMaxDynamicSharedMemorySize, SMEM_INNER);
    cudaFuncSetAttribute(gemm_in_mma, cudaFuncAttributeMaxDynamicSharedMemorySize, SMEM_MMA);
    cudaFuncSetAttribute(gemm_out_mma, cudaFuncAttributeMaxDynamicSharedMemorySize, SMEM_MMA);

    gates_kernel<<<1, 32>>>(gate_logits);
    bias_kernel<<<5, 512>>>(in_proj_w, pre_b[0], pre_b[1], pre_b[2], pre_b[3],
                            post_b[0], post_b[1], post_b[2], post_b[3]);
    tok_split<<<12544, 256>>>(tokens);
    fuse_gemm_all<<<dim3(4, 4, 8), 256>>>(in_proj_w, pre_w[0], pre_w[1], pre_w[2], pre_w[3],
                                          out_proj_w, post_w[0], post_w[1], post_w[2], post_w[3]);
    gemm_in_mma<<<dim3(4, 196, 4), 256, SMEM_MMA>>>();
    mamba_inner<<<2048, 256, SMEM_INNER>>>(conv_x_w, conv_x_b, conv_z_w, conv_z_b,
                                           x_proj_w, ln_w, ln_b, dt_proj_w, dt_proj_b,
                                           A_log, D_param);
    gemm_out_mma<<<dim3(4, 196), 256, SMEM_MMA>>>(out);
    (void)n_in; (void)out_size;
}

// round 8
// speedup vs baseline: 1.4409x; 1.2685x over previous
#include <cuda_runtime.h>
#include <cuda_bf16.h>
#include <math.h>
#include <stdint.h>

#define NPOS 49
#define DIMV 512
#define DHALF 256
#define EDIM 48
#define TOK_PER_G 25088            // 512*49
#define SLAB 12845056              // 25088*512 (elements)
#define WSZ 262144                 // 512*512

// ---------------- device scratch (no allocations allowed) ----------------
__device__ float g_xz[51380224];                         // (2048, 49, 512) fp32
__device__ __align__(16) __nv_bfloat16 g_tok_h[12845056];
__device__ __align__(16) __nv_bfloat16 g_tok_l[12845056];
__device__ __align__(16) __nv_bfloat16 g_yc_h[51380224];
__device__ __align__(16) __nv_bfloat16 g_yc_l[51380224];
__device__ __align__(16) __nv_bfloat16 g_Wc_h[4 * WSZ];
__device__ __align__(16) __nv_bfloat16 g_Wc_l[4 * WSZ];
__device__ __align__(16) __nv_bfloat16 g_Wo_h[4 * WSZ];
__device__ __align__(16) __nv_bfloat16 g_Wo_l[4 * WSZ];
__device__ float g_bc[4 * DIMV];
__device__ float g_outb[DIMV];
__device__ float g_gates[4];

__constant__ int c_diag[49] = {0,1,7,2,8,14,3,9,15,21,4,10,16,22,28,5,11,17,23,29,35,
                               6,12,18,24,30,36,42,13,19,25,31,37,43,20,26,32,38,44,
                               27,33,39,45,34,40,46,41,47,48};
__constant__ int c_anti[49] = {6,5,13,4,12,20,3,11,19,27,2,10,18,26,34,1,9,17,25,33,41,
                               0,8,16,24,32,40,48,7,15,23,31,39,47,14,22,30,38,46,
                               21,29,37,45,28,36,44,35,43,42};

// ---------------- mma.sync / cp.async helpers (baseline PTX, valid on sm_103) ----------------
__device__ __forceinline__ uint32_t smem_u32(const void* p) {
    uint32_t a;
    asm("{ .reg .u64 t; cvta.to.shared.u64 t, %1; cvt.u32.u64 %0, t; }" : "=r"(a) : "l"(p));
    return a;
}
__device__ __forceinline__ void ldsm_x4(uint32_t* r, uint32_t addr) {
    asm volatile("ldmatrix.sync.aligned.m8n8.x4.shared.b16 {%0,%1,%2,%3}, [%4];"
                 : "=r"(r[0]), "=r"(r[1]), "=r"(r[2]), "=r"(r[3]) : "r"(addr));
}
__device__ __forceinline__ void mma16816(float* c, const uint32_t* a, const uint32_t* b) {
    asm volatile(
        "mma.sync.aligned.m16n8k16.row.col.f32.bf16.bf16.f32 "
        "{%0,%1,%2,%3}, {%4,%5,%6,%7}, {%8,%9}, {%0,%1,%2,%3};"
        : "+f"(c[0]), "+f"(c[1]), "+f"(c[2]), "+f"(c[3])
        : "r"(a[0]), "r"(a[1]), "r"(a[2]), "r"(a[3]), "r"(b[0]), "r"(b[1]));
}
__device__ __forceinline__ void cpa16(uint32_t d, const void* s) {
    asm volatile("cp.async.cg.shared.global [%0], [%1], 16;" :: "r"(d), "l"(s));
}
#define CP_COMMIT() asm volatile("cp.async.commit_group;" ::: "memory")
#define CP_WAIT1()  asm volatile("cp.async.wait_group 1;" ::: "memory")
#define CP_WAIT0()  asm volatile("cp.async.wait_group 0;" ::: "memory")

// smem layout per stage (bytes): Ah 0, Al 10240, Bh 20480, Bl 30720; stage stride 40960
#define ST_STRIDE 40960
#define SMEM_MMA 81920
#define ROWB 80            // bytes per padded row (40 halves)

// ---------------- small prep kernels ----------------
__global__ void gates_kernel(const float* __restrict__ gl) {
    if (threadIdx.x == 0) {
        float m = fmaxf(fmaxf(gl[0], gl[1]), fmaxf(gl[2], gl[3]));
        float e0 = expf(gl[0] - m), e1 = expf(gl[1] - m), e2 = expf(gl[2] - m), e3 = expf(gl[3] - m);
        float s = e0 + e1 + e2 + e3;
        g_gates[0] = e0 / s; g_gates[1] = e1 / s; g_gates[2] = e2 / s; g_gates[3] = e3 / s;
    }
}

__global__ void bias_kernel(const float* __restrict__ in_proj_w,
                            const float* __restrict__ bh, const float* __restrict__ bv,
                            const float* __restrict__ bd, const float* __restrict__ ba,
                            const float* __restrict__ ph, const float* __restrict__ pv,
                            const float* __restrict__ pd, const float* __restrict__ pa) {
    int blk = blockIdx.x;
    int j = threadIdx.x;
    if (blk < 4) {
        const float* pb = (blk == 0) ? bh : (blk == 1) ? bv : (blk == 2) ? bd : ba;
        float s = 0.f;
        const float* row = in_proj_w + j * DIMV;
        for (int k = 0; k < DIMV; k++) s += row[k] * pb[k];
        g_bc[blk * DIMV + j] = s;
    } else {
        g_outb[j] = g_gates[0]*ph[j] + g_gates[1]*pv[j] + g_gates[2]*pd[j] + g_gates[3]*pa[j];
    }
}

// tokens fp32 -> bf16 hi/lo
__global__ __launch_bounds__(256) void tok_split(const float* __restrict__ tk) {
    size_t i = ((size_t)blockIdx.x * 256 + threadIdx.x) * 4;
    float4 v = *(const float4*)(tk + i);
    __nv_bfloat16 h0 = __float2bfloat16(v.x), h1 = __float2bfloat16(v.y);
    __nv_bfloat16 h2 = __float2bfloat16(v.z), h3 = __float2bfloat16(v.w);
    __nv_bfloat16 l0 = __float2bfloat16(v.x - __bfloat162float(h0));
    __nv_bfloat16 l1 = __float2bfloat16(v.y - __bfloat162float(h1));
    __nv_bfloat16 l2 = __float2bfloat16(v.z - __bfloat162float(h2));
    __nv_bfloat16 l3 = __float2bfloat16(v.w - __bfloat162float(h3));
    *(__nv_bfloat162*)(g_tok_h + i)     = __nv_bfloat162(h0, h1);
    *(__nv_bfloat162*)(g_tok_h + i + 2) = __nv_bfloat162(h2, h3);
    *(__nv_bfloat162*)(g_tok_l + i)     = __nv_bfloat162(l0, l1);
    *(__nv_bfloat162*)(g_tok_l + i + 2) = __nv_bfloat162(l2, l3);
}

// ---------------- batched weight-fusion GEMM (8 products, one launch) ----------------
#define BKT 8
#define GEMM_COMPUTE(As, Bs, acc, tx, ty)                                     \
    _Pragma("unroll")                                                         \
    for (int kk = 0; kk < BKT; kk++) {                                        \
        float ar[8], br[8];                                                   \
        *(float4*)(ar)     = *(const float4*)&As[kk][(ty) * 8];               \
        *(float4*)(ar + 4) = *(const float4*)&As[kk][(ty) * 8 + 4];           \
        *(float4*)(br)     = *(const float4*)&Bs[kk][(tx) * 8];               \
        *(float4*)(br + 4) = *(const float4*)&Bs[kk][(tx) * 8 + 4];           \
        _Pragma("unroll")                                                     \
        for (int ii = 0; ii < 8; ii++)                                        \
            _Pragma("unroll")                                                 \
            for (int jj = 0; jj < 8; jj++) acc[ii][jj] += ar[ii] * br[jj];    \
    }

__global__ __launch_bounds__(256) void fuse_gemm_all(
    const float* __restrict__ in_proj, const float* __restrict__ p0,
    const float* __restrict__ p1, const float* __restrict__ p2, const float* __restrict__ p3,
    const float* __restrict__ outp, const float* __restrict__ q0,
    const float* __restrict__ q1, const float* __restrict__ q2, const float* __restrict__ q3) {
    __shared__ float As[BKT][128];
    __shared__ float Bs[BKT][128];
    int z = blockIdx.z;
    const float* A; const float* B;
    __nv_bfloat16 *Ch, *Cl; float scale;
    if (z < 4) {
        A = in_proj;
        B = (z == 0) ? p0 : (z == 1) ? p1 : (z == 2) ? p2 : p3;
        Ch = g_Wc_h + z * WSZ; Cl = g_Wc_l + z * WSZ; scale = 1.f;
    } else {
        int g = z - 4;
        A = (g == 0) ? q0 : (g == 1) ? q1 : (g == 2) ? q2 : q3;
        B = outp;
        Ch = g_Wo_h + g * WSZ; Cl = g_Wo_l + g * WSZ; scale = g_gates[g];
    }
    int tid = threadIdx.x;
    int n0 = blockIdx.x * 128, m0 = blockIdx.y * 128;
    int tx = tid & 15, ty = tid >> 4;
    int lr = tid >> 1, lk4 = (tid & 1) * 4;
    int bk = tid >> 5, bc4 = (tid & 31) * 4;
    float acc[8][8] = {};
    const float* Arow = A + (m0 + lr) * DIMV + lk4;

    float4 av = *(const float4*)(Arow);
    float4 bv = *(const float4*)(B + bk * DIMV + n0 + bc4);
    for (int k0 = 0; k0 < DIMV; k0 += BKT) {
        As[lk4 + 0][lr] = av.x; As[lk4 + 1][lr] = av.y;
        As[lk4 + 2][lr] = av.z; As[lk4 + 3][lr] = av.w;
        *(float4*)&Bs[bk][bc4] = bv;
        __syncthreads();
        int k1 = k0 + BKT;
        if (k1 < DIMV) {
            av = *(const float4*)(Arow + k1);
            bv = *(const float4*)(B + (k1 + bk) * DIMV + n0 + bc4);
        }
        GEMM_COMPUTE(As, Bs, acc, tx, ty)
        __syncthreads();
    }
    #pragma unroll
    for (int i = 0; i < 8; i++) {
        int row = m0 + ty * 8 + i;
        #pragma unroll
        for (int j = 0; j < 8; j++) {
            float v = acc[i][j] * scale;
            __nv_bfloat16 h = __float2bfloat16(v);
            __nv_bfloat16 l = __float2bfloat16(v - __bfloat162float(h));
            Ch[row * DIMV + n0 + tx * 8 + j] = h;
            Cl[row * DIMV + n0 + tx * 8 + j] = l;
        }
    }
}

// ---------------- HMMA split-bf16 core ----------------
// one 128x128x32 chunk from stage smem into acc; B-frags short-lived (reg diet)
__device__ __forceinline__ void mma_chunk(uint32_t sbase, float acc[2][8][4],
                                          int wm, int wn, int l) {
    #pragma unroll
    for (int ks = 0; ks < 2; ks++) {
        int ko = ks * 32;  // bytes (16 halves)
        uint32_t ah[2][4], al[2][4];
        #pragma unroll
        for (int mt = 0; mt < 2; mt++) {
            int row = wm * 32 + mt * 16 + (l & 15);
            uint32_t ad = sbase + row * ROWB + ko + ((l >> 4) * 16);
            ldsm_x4(ah[mt], ad);
            ldsm_x4(al[mt], ad + 10240);
        }
        #pragma unroll
        for (int np = 0; np < 4; np++) {
            uint32_t bh4[4], bl4[4];
            int nrow = wn * 64 + np * 16 + (l & 7) + ((l >> 4) << 3);
            uint32_t bd = sbase + 20480 + nrow * ROWB + ko + (((l >> 3) & 1) * 16);
            ldsm_x4(bh4, bd);
            ldsm_x4(bl4, bd + 10240);
            #pragma unroll
            for (int mt = 0; mt < 2; mt++)
                #pragma unroll
                for (int hf = 0; hf < 2; hf++) {
                    int nt = np * 2 + hf;
                    mma16816(acc[mt][nt], ah[mt], &bh4[hf * 2]);
                    mma16816(acc[mt][nt], ah[mt], &bl4[hf * 2]);
                    mma16816(acc[mt][nt], al[mt], &bh4[hf * 2]);
                }
        }
    }
}

// Input GEMM: xz[g*25088+m, n] = sum_k tok[gather(m), k] * Wc_g[n, k] + bc_g[n]
__global__ __launch_bounds__(256, 2) void gemm_in_mma() {
    extern __shared__ char smem[];
    const int t = threadIdx.x;
    const int w = t >> 5, l = t & 31;
    const int wm = w & 3, wn = w >> 2;
    const int n0 = blockIdx.x * 128, m0 = blockIdx.y * 128, g = blockIdx.z;

    const int lr0 = t >> 2;
    const int seg = (t & 3) * 8;     // halves
    size_t aG[2], bG[2];
    #pragma unroll
    for (int p = 0; p < 2; p++) {
        int r = lr0 + p * 64;
        int m = m0 + r;
        int bi = m / NPOS, ll = m - bi * NPOS;
        int srcl = ll;
        if (g == 1) srcl = (ll % 7) * 7 + ll / 7;
        else if (g == 2) srcl = c_diag[ll];
        else if (g == 3) srcl = c_anti[ll];
        aG[p] = (size_t)(bi * NPOS + srcl) * DIMV + seg;
        bG[p] = (size_t)g * WSZ + (size_t)(n0 + r) * DIMV + seg;
    }
    const int sOff0 = (lr0 * 40 + seg) * 2;          // bytes
    const int sOff1 = ((lr0 + 64) * 40 + seg) * 2;
    const uint32_t sb32 = smem_u32(smem);

    float acc[2][8][4];
    #pragma unroll
    for (int i = 0; i < 2; i++)
        #pragma unroll
        for (int j = 0; j < 8; j++)
            #pragma unroll
            for (int q = 0; q < 4; q++) acc[i][j][q] = 0.f;

    #define ISSUE_IN(stage, c)                                                   \
        do {                                                                     \
            uint32_t st_ = sb32 + (stage) * ST_STRIDE;                           \
            int kc_ = (c) * 32;                                                  \
            cpa16(st_ + sOff0,         g_tok_h + aG[0] + kc_);                   \
            cpa16(st_ + sOff1,         g_tok_h + aG[1] + kc_);                   \
            cpa16(st_ + 10240 + sOff0, g_tok_l + aG[0] + kc_);                   \
            cpa16(st_ + 10240 + sOff1, g_tok_l + aG[1] + kc_);                   \
            cpa16(st_ + 20480 + sOff0, g_Wc_h + bG[0] + kc_);                    \
            cpa16(st_ + 20480 + sOff1, g_Wc_h + bG[1] + kc_);                    \
            cpa16(st_ + 30720 + sOff0, g_Wc_l + bG[0] + kc_);                    \
            cpa16(st_ + 30720 + sOff1, g_Wc_l + bG[1] + kc_);                    \
            CP_COMMIT();                                                         \
        } while (0)

    ISSUE_IN(0, 0);
    for (int c = 0; c < 16; c++) {
        if (c + 1 < 16) { ISSUE_IN((c + 1) & 1, c + 1); CP_WAIT1(); }
        else            { CP_WAIT0(); }
        __syncthreads();
        mma_chunk(sb32 + (c & 1) * ST_STRIDE, acc, wm, wn, l);
        __syncthreads();
    }
    #undef ISSUE_IN

    int lrow = l >> 2, lcol = (l & 3) * 2;
    #pragma unroll
    for (int mt = 0; mt < 2; mt++) {
        int m = m0 + wm * 32 + mt * 16 + lrow;
        float* dbase = g_xz + (size_t)(g * TOK_PER_G + m) * DIMV;
        #pragma unroll
        for (int nt = 0; nt < 8; nt++) {
            int n = n0 + wn * 64 + nt * 8 + lcol;
            float b0 = g_bc[g * DIMV + n], b1 = g_bc[g * DIMV + n + 1];
            dbase[n]              = acc[mt][nt][0] + b0;
            dbase[n + 1]          = acc[mt][nt][1] + b1;
            dbase[8 * DIMV + n]     = acc[mt][nt][2] + b0;
            dbase[8 * DIMV + n + 1] = acc[mt][nt][3] + b1;
        }
    }
}

// Output GEMM: out[m, n] = outb[n] + sum_g sum_k ycat[g*25088+m, k] * Wo_g[n, k]
__global__ __launch_bounds__(256, 2) void gemm_out_mma(float* __restrict__ out) {
    extern __shared__ char smem[];
    const int t = threadIdx.x;
    const int w = t >> 5, l = t & 31;
    const int wm = w & 3, wn = w >> 2;
    const int n0 = blockIdx.x * 128, m0 = blockIdx.y * 128;

    const int lr0 = t >> 2;
    const int seg = (t & 3) * 8;
    size_t aG[2], bG[2];
    #pragma unroll
    for (int p = 0; p < 2; p++) {
        int r = lr0 + p * 64;
        aG[p] = (size_t)(m0 + r) * DIMV + seg;
        bG[p] = (size_t)(n0 + r) * DIMV + seg;
    }
    const int sOff0 = (lr0 * 40 + seg) * 2;
    const int sOff1 = ((lr0 + 64) * 40 + seg) * 2;
    const uint32_t sb32 = smem_u32(smem);

    float acc[2][8][4];
    #pragma unroll
    for (int i = 0; i < 2; i++)
        #pragma unroll
        for (int j = 0; j < 8; j++)
            #pragma unroll
            for (int q = 0; q < 4; q++) acc[i][j][q] = 0.f;

    #define ISSUE_OUT(stage, c)                                                  \
        do {                                                                     \
            uint32_t st_ = sb32 + (stage) * ST_STRIDE;                           \
            size_t aS_ = (size_t)((c) >> 4) * SLAB + (size_t)((c) & 15) * 32;    \
            size_t bS_ = (size_t)((c) >> 4) * WSZ + (size_t)((c) & 15) * 32;     \
            cpa16(st_ + sOff0,         g_yc_h + aS_ + aG[0]);                    \
            cpa16(st_ + sOff1,         g_yc_h + aS_ + aG[1]);                    \
            cpa16(st_ + 10240 + sOff0, g_yc_l + aS_ + aG[0]);                    \
            cpa16(st_ + 10240 + sOff1, g_yc_l + aS_ + aG[1]);                    \
            cpa16(st_ + 20480 + sOff0, g_Wo_h + bS_ + bG[0]);                    \
            cpa16(st_ + 20480 + sOff1, g_Wo_h + bS_ + bG[1]);                    \
            cpa16(st_ + 30720 + sOff0, g_Wo_l + bS_ + bG[0]);                    \
            cpa16(st_ + 30720 + sOff1, g_Wo_l + bS_ + bG[1]);                    \
            CP_COMMIT();                                                         \
        } while (0)

    ISSUE_OUT(0, 0);
    for (int c = 0; c < 64; c++) {
        if (c + 1 < 64) { ISSUE_OUT((c + 1) & 1, c + 1); CP_WAIT1(); }
        else            { CP_WAIT0(); }
        __syncthreads();
        mma_chunk(sb32 + (c & 1) * ST_STRIDE, acc, wm, wn, l);
        __syncthreads();
    }
    #undef ISSUE_OUT

    int lrow = l >> 2, lcol = (l & 3) * 2;
    #pragma unroll
    for (int mt = 0; mt < 2; mt++) {
        int m = m0 + wm * 32 + mt * 16 + lrow;
        float* dbase = out + (size_t)m * DIMV;
        #pragma unroll
        for (int nt = 0; nt < 8; nt++) {
            int n = n0 + wn * 64 + nt * 8 + lcol;
            float b0 = g_outb[n], b1 = g_outb[n + 1];
            dbase[n]              = acc[mt][nt][0] + b0;
            dbase[n + 1]          = acc[mt][nt][1] + b1;
            dbase[8 * DIMV + n]     = acc[mt][nt][2] + b0;
            dbase[8 * DIMV + n + 1] = acc[mt][nt][3] + b1;
        }
    }
}

// ---------------- fused mamba inner (smem: x path only -> 2 CTAs/SM) ----------------
__global__ __launch_bounds__(256, 2) void mamba_inner(
    const float* __restrict__ cxw, const float* __restrict__ cxb,
    const float* __restrict__ czw, const float* __restrict__ czb,
    const float* __restrict__ xpw, const float* __restrict__ lnw, const float* __restrict__ lnb,
    const float* __restrict__ dtw, const float* __restrict__ dtb,
    const float* __restrict__ Alog, const float* __restrict__ Dp) {
    extern __shared__ float sm[];
    float* sx   = sm;                 // 256*49
    float* sdbl = sm + 12544;         // 49*48
    float* sxp  = sm + 14896;         // 256*48
    int b = blockIdx.x;
    int t = threadIdx.x;
    const float* base = g_xz + (size_t)b * NPOS * DIMV;
    size_t ybase = (size_t)b * NPOS * DIMV;

    // load x half (token-major) into channel-major smem
    for (int l = 0; l < NPOS; l++)
        sx[t * NPOS + l] = base[l * DIMV + t];
    // transpose x_proj_w into smem [d][e]
    for (int i = t; i < EDIM * DHALF; i += 256) {
        int e = i >> 8, d = i & 255;
        sxp[d * EDIM + e] = xpw[i];
    }
    // x conv k=3 SAME + SiLU, in place
    {
        float w0 = cxw[t * 3], w1 = cxw[t * 3 + 1], w2 = cxw[t * 3 + 2], bb = cxb[t];
        float prev = 0.f;
        for (int l = 0; l < NPOS; l++) {
            float cur = sx[t * NPOS + l];
            float nxt = (l < NPOS - 1) ? sx[t * NPOS + l + 1] : 0.f;
            float v = w0 * prev + w1 * cur + w2 * nxt + bb;
            v = v / (1.f + expf(-v));
            prev = cur;
            sx[t * NPOS + l] = v;
        }
    }
    // z path: stream from global (rolling window), conv+silu, write bf16 hi/lo
    {
        float w0 = czw[t * 3], w1 = czw[t * 3 + 1], w2 = czw[t * 3 + 2], bb = czb[t];
        const float* zb = base + DHALF + t;
        float prev = 0.f, cur = zb[0];
        for (int l = 0; l < NPOS; l++) {
            float nxt = (l < NPOS - 1) ? zb[(size_t)(l + 1) * DIMV] : 0.f;
            float v = w0 * prev + w1 * cur + w2 * nxt + bb;
            v = v / (1.f + expf(-v));
            prev = cur; cur = nxt;
            size_t idx = ybase + (size_t)l * DIMV + DHALF + t;
            __nv_bfloat16 hz = __float2bfloat16(v);
            g_yc_h[idx] = hz;
            g_yc_l[idx] = __float2bfloat16(v - __bfloat162float(hz));
        }
    }
    __syncthreads();

    // x_dbl[l][e] = sum_d x_conv[d][l] * xp[e][d]
    for (int task = t; task < NPOS * 6; task += 256) {
        int l = task / 6, ec = task % 6;
        float acc[8] = {};
        for (int d = 0; d < DHALF; d++) {
            float xv = sx[d * NPOS + l];
            float4 p0 = *(const float4*)&sxp[d * EDIM + ec * 8];
            float4 p1 = *(const float4*)&sxp[d * EDIM + ec * 8 + 4];
            acc[0] += xv * p0.x; acc[1] += xv * p0.y; acc[2] += xv * p0.z; acc[3] += xv * p0.w;
            acc[4] += xv * p1.x; acc[5] += xv * p1.y; acc[6] += xv * p1.z; acc[7] += xv * p1.w;
        }
        #pragma unroll
        for (int j = 0; j < 8; j++) sdbl[l * EDIM + ec * 8 + j] = acc[j];
    }
    __syncthreads();

    if (t < NPOS) {
        float* row = &sdbl[t * EDIM];
        float m = 0.f;
        for (int e = 0; e < EDIM; e++) m += row[e];
        m *= (1.f / EDIM);
        float v = 0.f;
        for (int e = 0; e < EDIM; e++) { float d = row[e] - m; v += d * d; }
        v *= (1.f / EDIM);
        float rs = rsqrtf(v + 1e-5f);
        for (int e = 0; e < EDIM; e++) row[e] = (row[e] - m) * rs * lnw[e] + lnb[e];
    }
    __syncthreads();

    float wreg[32];
    #pragma unroll
    for (int r = 0; r < 32; r += 4)
        *(float4*)&wreg[r] = *(const float4*)&dtw[t * 32 + r];
    float a[8];
    #pragma unroll
    for (int n = 0; n < 8; n++) a[n] = -expf(Alog[t * 8 + n]);
    float Dv = Dp[t], bias = dtb[t];
    float h[8] = {};
    for (int l = 0; l < NPOS; l++) {
        const float* rowp = &sdbl[l * EDIM];
        float u = sx[t * NPOS + l];
        float s = bias;
        #pragma unroll
        for (int r = 0; r < 32; r += 4) {
            float4 x4 = *(const float4*)&rowp[r];
            s += wreg[r] * x4.x + wreg[r + 1] * x4.y + wreg[r + 2] * x4.z + wreg[r + 3] * x4.w;
        }
        float dt = (s > 20.f) ? s : log1pf(expf(s));
        float y = 0.f;
        #pragma unroll
        for (int n = 0; n < 8; n++) {
            float Bn = rowp[32 + n], Cn = rowp[40 + n];
            h[n] = h[n] * expf(dt * a[n]) + dt * Bn * u;
            y += h[n] * Cn;
        }
        y += Dv * u;
        if (isnan(y)) y = 0.f;
        else if (isinf(y)) y = (y > 0.f) ? 3.402823466e38f : -3.402823466e38f;
        size_t idx = ybase + (size_t)l * DIMV + t;
        __nv_bfloat16 hy = __float2bfloat16(y);
        g_yc_h[idx] = hy;
        g_yc_l[idx] = __float2bfloat16(y - __bfloat162float(hy));
    }
}

// ---------------- host launcher ----------------
extern "C" void kernel_launch(void* const* d_in, const int* in_sizes, int n_in,
                              void* d_out, int out_size) {
    int dict_order = (in_sizes[10] != 768);

    const float* tokens = (const float*)d_in[0];
    const float* pre_w[4], *pre_b[4], *post_w[4], *post_b[4];
    const float *in_proj_w, *conv_x_w, *conv_x_b, *conv_z_w, *conv_z_b;
    const float *x_proj_w, *ln_w, *ln_b, *dt_proj_w, *dt_proj_b;
    const float *A_log, *D_param, *out_proj_w, *gate_logits;

    for (int g = 0; g < 4; g++) {
        pre_w[g] = (const float*)d_in[1 + 2 * g];
        pre_b[g] = (const float*)d_in[2 + 2 * g];
    }
    if (dict_order) {
        for (int g = 0; g < 4; g++) {
            post_w[g] = (const float*)d_in[9 + 2 * g];
            post_b[g] = (const float*)d_in[10 + 2 * g];
        }
        in_proj_w  = (const float*)d_in[17];
        conv_x_w   = (const float*)d_in[18];
        conv_x_b   = (const float*)d_in[19];
        conv_z_w   = (const float*)d_in[20];
        conv_z_b   = (const float*)d_in[21];
        x_proj_w   = (const float*)d_in[22];
        ln_w       = (const float*)d_in[23];
        ln_b       = (const float*)d_in[24];
        dt_proj_w  = (const float*)d_in[25];
        dt_proj_b  = (const float*)d_in[26];
        A_log      = (const float*)d_in[27];
        D_param    = (const float*)d_in[28];
        out_proj_w = (const float*)d_in[29];
        gate_logits = (const float*)d_in[30];
    } else {
        in_proj_w  = (const float*)d_in[9];
        conv_x_w   = (const float*)d_in[10];
        conv_x_b   = (const float*)d_in[11];
        conv_z_w   = (const float*)d_in[12];
        conv_z_b   = (const float*)d_in[13];
        x_proj_w   = (const float*)d_in[14];
        ln_w       = (const float*)d_in[15];
        ln_b       = (const float*)d_in[16];
        dt_proj_w  = (const float*)d_in[17];
        dt_proj_b  = (const float*)d_in[18];
        A_log      = (const float*)d_in[19];
        D_param    = (const float*)d_in[20];
        out_proj_w = (const float*)d_in[21];
        for (int g = 0; g < 4; g++) {
            post_w[g] = (const float*)d_in[22 + 2 * g];
            post_b[g] = (const float*)d_in[23 + 2 * g];
        }
        gate_logits = (const float*)d_in[30];
    }
    float* out = (float*)d_out;

    const int SMEM_INNER = (12544 + 2352 + 12288) * 4;  // 108,736 B
    cudaFuncSetAttribute(mamba_inner, cudaFuncAttributeMaxDynamicSharedMemorySize, SMEM_INNER);
    cudaFuncSetAttribute(gemm_in_mma, cudaFuncAttributeMaxDynamicSharedMemorySize, SMEM_MMA);
    cudaFuncSetAttribute(gemm_out_mma, cudaFuncAttributeMaxDynamicSharedMemorySize, SMEM_MMA);

    gates_kernel<<<1, 32>>>(gate_logits);
    bias_kernel<<<5, 512>>>(in_proj_w, pre_b[0], pre_b[1], pre_b[2], pre_b[3],
                            post_b[0], post_b[1], post_b[2], post_b[3]);
    tok_split<<<12544, 256>>>(tokens);
    fuse_gemm_all<<<dim3(4, 4, 8), 256>>>(in_proj_w, pre_w[0], pre_w[1], pre_w[2], pre_w[3],
                                          out_proj_w, post_w[0], post_w[1], post_w[2], post_w[3]);
    gemm_in_mma<<<dim3(4, 196, 4), 256, SMEM_MMA>>>();
    mamba_inner<<<2048, 256, SMEM_INNER>>>(conv_x_w, conv_x_b, conv_z_w, conv_z_b,
                                           x_proj_w, ln_w, ln_b, dt_proj_w, dt_proj_b,
                                           A_log, D_param);
    gemm_out_mma<<<dim3(4, 196), 256, SMEM_MMA>>>(out);
    (void)n_in; (void)out_size;
}

// round 12
// speedup vs baseline: 2.6021x; 1.8059x over previous
#include <cuda_runtime.h>
#include <cuda_fp16.h>
#include <math.h>
#include <stdint.h>

#define NPOS 49
#define DIMV 512
#define DHALF 256
#define EDIM 48
#define TOK_PER_G 25088            // 512*49
#define SLAB 12845056              // 25088*512 (elements)
#define WSZ 262144                 // 512*512

// ---------------- device scratch (no allocations allowed) ----------------
__device__ float g_xz[51380224];                     // (2048, 49, 512) fp32
__device__ __align__(16) __half g_tok_h[12845056];
__device__ __align__(16) __half g_tok_l[12845056];
__device__ __align__(16) __half g_yc_h[51380224];
__device__ __align__(16) __half g_yc_l[51380224];
__device__ __align__(16) __half g_Wc_h[4 * WSZ];
__device__ __align__(16) __half g_Wo_h[4 * WSZ];
__device__ float g_bc[4 * DIMV];
__device__ float g_outb[DIMV];

__constant__ int c_diag[49] = {0,1,7,2,8,14,3,9,15,21,4,10,16,22,28,5,11,17,23,29,35,
                               6,12,18,24,30,36,42,13,19,25,31,37,43,20,26,32,38,44,
                               27,33,39,45,34,40,46,41,47,48};
__constant__ int c_anti[49] = {6,5,13,4,12,20,3,11,19,27,2,10,18,26,34,1,9,17,25,33,41,
                               0,8,16,24,32,40,48,7,15,23,31,39,47,14,22,30,38,46,
                               21,29,37,45,28,36,44,35,43,42};

// ---------------- mma.sync / cp.async helpers (baseline PTX, valid on sm_103) ----------------
__device__ __forceinline__ uint32_t smem_u32(const void* p) {
    uint32_t a;
    asm("{ .reg .u64 t; cvta.to.shared.u64 t, %1; cvt.u32.u64 %0, t; }" : "=r"(a) : "l"(p));
    return a;
}
__device__ __forceinline__ void ldsm_x4(uint32_t* r, uint32_t addr) {
    asm volatile("ldmatrix.sync.aligned.m8n8.x4.shared.b16 {%0,%1,%2,%3}, [%4];"
                 : "=r"(r[0]), "=r"(r[1]), "=r"(r[2]), "=r"(r[3]) : "r"(addr));
}
__device__ __forceinline__ void mma16816(float* c, const uint32_t* a, const uint32_t* b) {
    asm volatile(
        "mma.sync.aligned.m16n8k16.row.col.f32.f16.f16.f32 "
        "{%0,%1,%2,%3}, {%4,%5,%6,%7}, {%8,%9}, {%0,%1,%2,%3};"
        : "+f"(c[0]), "+f"(c[1]), "+f"(c[2]), "+f"(c[3])
        : "r"(a[0]), "r"(a[1]), "r"(a[2]), "r"(a[3]), "r"(b[0]), "r"(b[1]));
}
__device__ __forceinline__ void cpa16(uint32_t d, const void* s) {
    asm volatile("cp.async.cg.shared.global [%0], [%1], 16;" :: "r"(d), "l"(s));
}
#define CP_COMMIT() asm volatile("cp.async.commit_group;" ::: "memory")
#define CP_WAIT1()  asm volatile("cp.async.wait_group 1;" ::: "memory")
#define CP_WAIT0()  asm volatile("cp.async.wait_group 0;" ::: "memory")

// smem per stage (bytes): Ah 0, Al 10240, Bh 20480; 3 stages
#define ST_STRIDE 30720
#define SMEM_MMA 92160
#define ROWB 80            // bytes per padded row (40 halves)

// ---------------- small prep kernels ----------------
__device__ __forceinline__ float gate_val(const float* gl, int g) {
    float m = fmaxf(fmaxf(gl[0], gl[1]), fmaxf(gl[2], gl[3]));
    float e0 = expf(gl[0] - m), e1 = expf(gl[1] - m), e2 = expf(gl[2] - m), e3 = expf(gl[3] - m);
    float s = e0 + e1 + e2 + e3;
    float eg = (g == 0) ? e0 : (g == 1) ? e1 : (g == 2) ? e2 : e3;
    return eg / s;
}

__global__ void bias_kernel(const float* __restrict__ in_proj_w,
                            const float* __restrict__ bh, const float* __restrict__ bv,
                            const float* __restrict__ bd, const float* __restrict__ ba,
                            const float* __restrict__ ph, const float* __restrict__ pv,
                            const float* __restrict__ pd, const float* __restrict__ pa,
                            const float* __restrict__ gl) {
    int blk = blockIdx.x;
    int j = threadIdx.x;
    if (blk < 4) {
        const float* pb = (blk == 0) ? bh : (blk == 1) ? bv : (blk == 2) ? bd : ba;
        float s = 0.f;
        const float* row = in_proj_w + j * DIMV;
        for (int k = 0; k < DIMV; k++) s += row[k] * pb[k];
        g_bc[blk * DIMV + j] = s;
    } else {
        g_outb[j] = gate_val(gl, 0) * ph[j] + gate_val(gl, 1) * pv[j] +
                    gate_val(gl, 2) * pd[j] + gate_val(gl, 3) * pa[j];
    }
}

// tokens fp32 -> fp16 hi/lo
__global__ __launch_bounds__(256) void tok_split(const float* __restrict__ tk) {
    size_t i = ((size_t)blockIdx.x * 256 + threadIdx.x) * 4;
    float4 v = *(const float4*)(tk + i);
    __half h0 = __float2half(v.x), h1 = __float2half(v.y);
    __half h2 = __float2half(v.z), h3 = __float2half(v.w);
    __half l0 = __float2half(v.x - __half2float(h0));
    __half l1 = __float2half(v.y - __half2float(h1));
    __half l2 = __float2half(v.z - __half2float(h2));
    __half l3 = __float2half(v.w - __half2float(h3));
    *(__half2*)(g_tok_h + i)     = __half2(h0, h1);
    *(__half2*)(g_tok_h + i + 2) = __half2(h2, h3);
    *(__half2*)(g_tok_l + i)     = __half2(l0, l1);
    *(__half2*)(g_tok_l + i + 2) = __half2(l2, l3);
}

// ---------------- batched weight-fusion GEMM (8 products, one launch) ----------------
#define BKT 8
#define GEMM_COMPUTE(As, Bs, acc, tx, ty)                                     \
    _Pragma("unroll")                                                         \
    for (int kk = 0; kk < BKT; kk++) {                                        \
        float ar[8], br[8];                                                   \
        *(float4*)(ar)     = *(const float4*)&As[kk][(ty) * 8];               \
        *(float4*)(ar + 4) = *(const float4*)&As[kk][(ty) * 8 + 4];           \
        *(float4*)(br)     = *(const float4*)&Bs[kk][(tx) * 8];               \
        *(float4*)(br + 4) = *(const float4*)&Bs[kk][(tx) * 8 + 4];           \
        _Pragma("unroll")                                                     \
        for (int ii = 0; ii < 8; ii++)                                        \
            _Pragma("unroll")                                                 \
            for (int jj = 0; jj < 8; jj++) acc[ii][jj] += ar[ii] * br[jj];    \
    }

__global__ __launch_bounds__(256) void fuse_gemm_all(
    const float* __restrict__ in_proj, const float* __restrict__ p0,
    const float* __restrict__ p1, const float* __restrict__ p2, const float* __restrict__ p3,
    const float* __restrict__ outp, const float* __restrict__ q0,
    const float* __restrict__ q1, const float* __restrict__ q2, const float* __restrict__ q3,
    const float* __restrict__ gl) {
    __shared__ float As[BKT][128];
    __shared__ float Bs[BKT][128];
    int z = blockIdx.z;
    const float* A; const float* B;
    __half* Ch; float scale;
    if (z < 4) {
        A = in_proj;
        B = (z == 0) ? p0 : (z == 1) ? p1 : (z == 2) ? p2 : p3;
        Ch = g_Wc_h + z * WSZ; scale = 1.f;
    } else {
        int g = z - 4;
        A = (g == 0) ? q0 : (g == 1) ? q1 : (g == 2) ? q2 : q3;
        B = outp;
        Ch = g_Wo_h + g * WSZ; scale = gate_val(gl, g);
    }
    int tid = threadIdx.x;
    int n0 = blockIdx.x * 128, m0 = blockIdx.y * 128;
    int tx = tid & 15, ty = tid >> 4;
    int lr = tid >> 1, lk4 = (tid & 1) * 4;
    int bk = tid >> 5, bc4 = (tid & 31) * 4;
    float acc[8][8] = {};
    const float* Arow = A + (m0 + lr) * DIMV + lk4;

    float4 av = *(const float4*)(Arow);
    float4 bv = *(const float4*)(B + bk * DIMV + n0 + bc4);
    for (int k0 = 0; k0 < DIMV; k0 += BKT) {
        As[lk4 + 0][lr] = av.x; As[lk4 + 1][lr] = av.y;
        As[lk4 + 2][lr] = av.z; As[lk4 + 3][lr] = av.w;
        *(float4*)&Bs[bk][bc4] = bv;
        __syncthreads();
        int k1 = k0 + BKT;
        if (k1 < DIMV) {
            av = *(const float4*)(Arow + k1);
            bv = *(const float4*)(B + (k1 + bk) * DIMV + n0 + bc4);
        }
        GEMM_COMPUTE(As, Bs, acc, tx, ty)
        __syncthreads();
    }
    #pragma unroll
    for (int i = 0; i < 8; i++) {
        int row = m0 + ty * 8 + i;
        #pragma unroll
        for (int j = 0; j < 8; j++)
            Ch[row * DIMV + n0 + tx * 8 + j] = __float2half(acc[i][j] * scale);
    }
}

// ---------------- HMMA split-fp16 core: 2 passes (Ah@Bh + Al@Bh) ----------------
__device__ __forceinline__ void mma_chunk(uint32_t sbase, float acc[2][8][4],
                                          int wm, int wn, int l) {
    #pragma unroll
    for (int ks = 0; ks < 2; ks++) {
        int ko = ks * 32;  // bytes (16 halves)
        uint32_t ah[2][4], al[2][4];
        #pragma unroll
        for (int mt = 0; mt < 2; mt++) {
            int row = wm * 32 + mt * 16 + (l & 15);
            uint32_t ad = sbase + row * ROWB + ko + ((l >> 4) * 16);
            ldsm_x4(ah[mt], ad);
            ldsm_x4(al[mt], ad + 10240);
        }
        #pragma unroll
        for (int np = 0; np < 4; np++) {
            uint32_t bh4[4];
            int nrow = wn * 64 + np * 16 + (l & 7) + ((l >> 4) << 3);
            uint32_t bd = sbase + 20480 + nrow * ROWB + ko + (((l >> 3) & 1) * 16);
            ldsm_x4(bh4, bd);
            #pragma unroll
            for (int mt = 0; mt < 2; mt++)
                #pragma unroll
                for (int hf = 0; hf < 2; hf++) {
                    int nt = np * 2 + hf;
                    mma16816(acc[mt][nt], ah[mt], &bh4[hf * 2]);
                    mma16816(acc[mt][nt], al[mt], &bh4[hf * 2]);
                }
        }
    }
}

// Input GEMM: xz[g*25088+m, n] = sum_k tok[gather(m), k] * Wc_g[n, k] + bc_g[n]
__global__ __launch_bounds__(256, 2) void gemm_in_mma() {
    extern __shared__ char smem[];
    const int t = threadIdx.x;
    const int w = t >> 5, l = t & 31;
    const int wm = w & 3, wn = w >> 2;
    const int n0 = blockIdx.x * 128, m0 = blockIdx.y * 128, g = blockIdx.z;

    const int lr0 = t >> 2;
    const int seg = (t & 3) * 8;     // halves
    size_t aG[2], bG[2];
    #pragma unroll
    for (int p = 0; p < 2; p++) {
        int r = lr0 + p * 64;
        int m = m0 + r;
        int bi = m / NPOS, ll = m - bi * NPOS;
        int srcl = ll;
        if (g == 1) srcl = (ll % 7) * 7 + ll / 7;
        else if (g == 2) srcl = c_diag[ll];
        else if (g == 3) srcl = c_anti[ll];
        aG[p] = (size_t)(bi * NPOS + srcl) * DIMV + seg;
        bG[p] = (size_t)g * WSZ + (size_t)(n0 + r) * DIMV + seg;
    }
    const int sOff0 = (lr0 * 40 + seg) * 2;          // bytes
    const int sOff1 = ((lr0 + 64) * 40 + seg) * 2;
    const uint32_t sb32 = smem_u32(smem);

    float acc[2][8][4];
    #pragma unroll
    for (int i = 0; i < 2; i++)
        #pragma unroll
        for (int j = 0; j < 8; j++)
            #pragma unroll
            for (int q = 0; q < 4; q++) acc[i][j][q] = 0.f;

    #define ISSUE_IN(stage, c)                                                   \
        do {                                                                     \
            uint32_t st_ = sb32 + (stage) * ST_STRIDE;                           \
            int kc_ = (c) * 32;                                                  \
            cpa16(st_ + sOff0,         g_tok_h + aG[0] + kc_);                   \
            cpa16(st_ + sOff1,         g_tok_h + aG[1] + kc_);                   \
            cpa16(st_ + 10240 + sOff0, g_tok_l + aG[0] + kc_);                   \
            cpa16(st_ + 10240 + sOff1, g_tok_l + aG[1] + kc_);                   \
            cpa16(st_ + 20480 + sOff0, g_Wc_h + bG[0] + kc_);                    \
            cpa16(st_ + 20480 + sOff1, g_Wc_h + bG[1] + kc_);                    \
            CP_COMMIT();                                                         \
        } while (0)

    ISSUE_IN(0, 0);
    ISSUE_IN(1, 1);
    for (int c = 0; c < 16; c++) {
        if (c < 15) CP_WAIT1(); else CP_WAIT0();
        __syncthreads();
        if (c + 2 < 16) ISSUE_IN((c + 2) % 3, c + 2);
        mma_chunk(sb32 + (c % 3) * ST_STRIDE, acc, wm, wn, l);
    }
    #undef ISSUE_IN

    int lrow = l >> 2, lcol = (l & 3) * 2;
    #pragma unroll
    for (int mt = 0; mt < 2; mt++) {
        int m = m0 + wm * 32 + mt * 16 + lrow;
        float* dbase = g_xz + (size_t)(g * TOK_PER_G + m) * DIMV;
        #pragma unroll
        for (int nt = 0; nt < 8; nt++) {
            int n = n0 + wn * 64 + nt * 8 + lcol;
            float b0 = g_bc[g * DIMV + n], b1 = g_bc[g * DIMV + n + 1];
            dbase[n]              = acc[mt][nt][0] + b0;
            dbase[n + 1]          = acc[mt][nt][1] + b1;
            dbase[8 * DIMV + n]     = acc[mt][nt][2] + b0;
            dbase[8 * DIMV + n + 1] = acc[mt][nt][3] + b1;
        }
    }
}

// Output GEMM: out[m, n] = outb[n] + sum_g sum_k ycat[g*25088+m, k] * Wo_g[n, k]
__global__ __launch_bounds__(256, 2) void gemm_out_mma(float* __restrict__ out) {
    extern __shared__ char smem[];
    const int t = threadIdx.x;
    const int w = t >> 5, l = t & 31;
    const int wm = w & 3, wn = w >> 2;
    const int n0 = blockIdx.x * 128, m0 = blockIdx.y * 128;

    const int lr0 = t >> 2;
    const int seg = (t & 3) * 8;
    size_t aG[2], bG[2];
    #pragma unroll
    for (int p = 0; p < 2; p++) {
        int r = lr0 + p * 64;
        aG[p] = (size_t)(m0 + r) * DIMV + seg;
        bG[p] = (size_t)(n0 + r) * DIMV + seg;
    }
    const int sOff0 = (lr0 * 40 + seg) * 2;
    const int sOff1 = ((lr0 + 64) * 40 + seg) * 2;
    const uint32_t sb32 = smem_u32(smem);

    float acc[2][8][4];
    #pragma unroll
    for (int i = 0; i < 2; i++)
        #pragma unroll
        for (int j = 0; j < 8; j++)
            #pragma unroll
            for (int q = 0; q < 4; q++) acc[i][j][q] = 0.f;

    #define ISSUE_OUT(stage, c)                                                  \
        do {                                                                     \
            uint32_t st_ = sb32 + (stage) * ST_STRIDE;                           \
            size_t aS_ = (size_t)((c) >> 4) * SLAB + (size_t)((c) & 15) * 32;    \
            size_t bS_ = (size_t)((c) >> 4) * WSZ + (size_t)((c) & 15) * 32;     \
            cpa16(st_ + sOff0,         g_yc_h + aS_ + aG[0]);                    \
            cpa16(st_ + sOff1,         g_yc_h + aS_ + aG[1]);                    \
            cpa16(st_ + 10240 + sOff0, g_yc_l + aS_ + aG[0]);                    \
            cpa16(st_ + 10240 + sOff1, g_yc_l + aS_ + aG[1]);                    \
            cpa16(st_ + 20480 + sOff0, g_Wo_h + bS_ + bG[0]);                    \
            cpa16(st_ + 20480 + sOff1, g_Wo_h + bS_ + bG[1]);                    \
            CP_COMMIT();                                                         \
        } while (0)

    ISSUE_OUT(0, 0);
    ISSUE_OUT(1, 1);
    for (int c = 0; c < 64; c++) {
        if (c < 63) CP_WAIT1(); else CP_WAIT0();
        __syncthreads();
        if (c + 2 < 64) ISSUE_OUT((c + 2) % 3, c + 2);
        mma_chunk(sb32 + (c % 3) * ST_STRIDE, acc, wm, wn, l);
    }
    #undef ISSUE_OUT

    int lrow = l >> 2, lcol = (l & 3) * 2;
    #pragma unroll
    for (int mt = 0; mt < 2; mt++) {
        int m = m0 + wm * 32 + mt * 16 + lrow;
        float* dbase = out + (size_t)m * DIMV;
        #pragma unroll
        for (int nt = 0; nt < 8; nt++) {
            int n = n0 + wn * 64 + nt * 8 + lcol;
            float b0 = g_outb[n], b1 = g_outb[n + 1];
            dbase[n]              = acc[mt][nt][0] + b0;
            dbase[n + 1]          = acc[mt][nt][1] + b1;
            dbase[8 * DIMV + n]     = acc[mt][nt][2] + b0;
            dbase[8 * DIMV + n + 1] = acc[mt][nt][3] + b1;
        }
    }
}

// ---------------- fused mamba inner (x path in smem, 2 CTAs/SM) ----------------
__global__ __launch_bounds__(256, 2) void mamba_inner(
    const float* __restrict__ cxw, const float* __restrict__ cxb,
    const float* __restrict__ czw, const float* __restrict__ czb,
    const float* __restrict__ xpw, const float* __restrict__ lnw, const float* __restrict__ lnb,
    const float* __restrict__ dtw, const float* __restrict__ dtb,
    const float* __restrict__ Alog, const float* __restrict__ Dp) {
    extern __shared__ float sm[];
    float* sx   = sm;                 // 256*49
    float* sdbl = sm + 12544;         // 49*48
    float* sxp  = sm + 14896;         // 256*48
    int b = blockIdx.x;
    int t = threadIdx.x;
    const float* base = g_xz + (size_t)b * NPOS * DIMV;
    size_t ybase = (size_t)b * NPOS * DIMV;

    for (int l = 0; l < NPOS; l++)
        sx[t * NPOS + l] = base[l * DIMV + t];
    for (int i = t; i < EDIM * DHALF; i += 256) {
        int e = i >> 8, d = i & 255;
        sxp[d * EDIM + e] = xpw[i];
    }
    {
        float w0 = cxw[t * 3], w1 = cxw[t * 3 + 1], w2 = cxw[t * 3 + 2], bb = cxb[t];
        float prev = 0.f;
        for (int l = 0; l < NPOS; l++) {
            float cur = sx[t * NPOS + l];
            float nxt = (l < NPOS - 1) ? sx[t * NPOS + l + 1] : 0.f;
            float v = w0 * prev + w1 * cur + w2 * nxt + bb;
            v = v / (1.f + expf(-v));
            prev = cur;
            sx[t * NPOS + l] = v;
        }
    }
    {
        float w0 = czw[t * 3], w1 = czw[t * 3 + 1], w2 = czw[t * 3 + 2], bb = czb[t];
        const float* zb = base + DHALF + t;
        float prev = 0.f, cur = zb[0];
        for (int l = 0; l < NPOS; l++) {
            float nxt = (l < NPOS - 1) ? zb[(size_t)(l + 1) * DIMV] : 0.f;
            float v = w0 * prev + w1 * cur + w2 * nxt + bb;
            v = v / (1.f + expf(-v));
            prev = cur; cur = nxt;
            size_t idx = ybase + (size_t)l * DIMV + DHALF + t;
            __half hz = __float2half(v);
            g_yc_h[idx] = hz;
            g_yc_l[idx] = __float2half(v - __half2float(hz));
        }
    }
    __syncthreads();

    for (int task = t; task < NPOS * 6; task += 256) {
        int l = task / 6, ec = task % 6;
        float acc[8] = {};
        for (int d = 0; d < DHALF; d++) {
            float xv = sx[d * NPOS + l];
            float4 p0 = *(const float4*)&sxp[d * EDIM + ec * 8];
            float4 p1 = *(const float4*)&sxp[d * EDIM + ec * 8 + 4];
            acc[0] += xv * p0.x; acc[1] += xv * p0.y; acc[2] += xv * p0.z; acc[3] += xv * p0.w;
            acc[4] += xv * p1.x; acc[5] += xv * p1.y; acc[6] += xv * p1.z; acc[7] += xv * p1.w;
        }
        #pragma unroll
        for (int j = 0; j < 8; j++) sdbl[l * EDIM + ec * 8 + j] = acc[j];
    }
    __syncthreads();

    if (t < NPOS) {
        float* row = &sdbl[t * EDIM];
        float m = 0.f;
        for (int e = 0; e < EDIM; e++) m += row[e];
        m *= (1.f / EDIM);
        float v = 0.f;
        for (int e = 0; e < EDIM; e++) { float d = row[e] - m; v += d * d; }
        v *= (1.f / EDIM);
        float rs = rsqrtf(v + 1e-5f);
        for (int e = 0; e < EDIM; e++) row[e] = (row[e] - m) * rs * lnw[e] + lnb[e];
    }
    __syncthreads();

    float wreg[32];
    #pragma unroll
    for (int r = 0; r < 32; r += 4)
        *(float4*)&wreg[r] = *(const float4*)&dtw[t * 32 + r];
    float a[8];
    #pragma unroll
    for (int n = 0; n < 8; n++) a[n] = -expf(Alog[t * 8 + n]);
    float Dv = Dp[t], bias = dtb[t];
    float h[8] = {};
    for (int l = 0; l < NPOS; l++) {
        const float* rowp = &sdbl[l * EDIM];
        float u = sx[t * NPOS + l];
        float s = bias;
        #pragma unroll
        for (int r = 0; r < 32; r += 4) {
            float4 x4 = *(const float4*)&rowp[r];
            s += wreg[r] * x4.x + wreg[r + 1] * x4.y + wreg[r + 2] * x4.z + wreg[r + 3] * x4.w;
        }
        float dt = (s > 20.f) ? s : log1pf(expf(s));
        float y = 0.f;
        #pragma unroll
        for (int n = 0; n < 8; n++) {
            float Bn = rowp[32 + n], Cn = rowp[40 + n];
            h[n] = h[n] * expf(dt * a[n]) + dt * Bn * u;
            y += h[n] * Cn;
        }
        y += Dv * u;
        if (isnan(y)) y = 0.f;
        // clamp only at fp16-inf boundary (reference clamps inf to 3.4e38;
        // finite |y| above 65000 would round to inf in fp16)
        else if (y > 65000.f) y = 65000.f;
        else if (y < -65000.f) y = -65000.f;
        size_t idx = ybase + (size_t)l * DIMV + t;
        __half hy = __float2half(y);
        g_yc_h[idx] = hy;
        g_yc_l[idx] = __float2half(y - __half2float(hy));
    }
}

// ---------------- host launcher ----------------
extern "C" void kernel_launch(void* const* d_in, const int* in_sizes, int n_in,
                              void* d_out, int out_size) {
    int dict_order = (in_sizes[10] != 768);

    const float* tokens = (const float*)d_in[0];
    const float* pre_w[4], *pre_b[4], *post_w[4], *post_b[4];
    const float *in_proj_w, *conv_x_w, *conv_x_b, *conv_z_w, *conv_z_b;
    const float *x_proj_w, *ln_w, *ln_b, *dt_proj_w, *dt_proj_b;
    const float *A_log, *D_param, *out_proj_w, *gate_logits;

    for (int g = 0; g < 4; g++) {
        pre_w[g] = (const float*)d_in[1 + 2 * g];
        pre_b[g] = (const float*)d_in[2 + 2 * g];
    }
    if (dict_order) {
        for (int g = 0; g < 4; g++) {
            post_w[g] = (const float*)d_in[9 + 2 * g];
            post_b[g] = (const float*)d_in[10 + 2 * g];
        }
        in_proj_w  = (const float*)d_in[17];
        conv_x_w   = (const float*)d_in[18];
        conv_x_b   = (const float*)d_in[19];
        conv_z_w   = (const float*)d_in[20];
        conv_z_b   = (const float*)d_in[21];
        x_proj_w   = (const float*)d_in[22];
        ln_w       = (const float*)d_in[23];
        ln_b       = (const float*)d_in[24];
        dt_proj_w  = (const float*)d_in[25];
        dt_proj_b  = (const float*)d_in[26];
        A_log      = (const float*)d_in[27];
        D_param    = (const float*)d_in[28];
        out_proj_w = (const float*)d_in[29];
        gate_logits = (const float*)d_in[30];
    } else {
        in_proj_w  = (const float*)d_in[9];
        conv_x_w   = (const float*)d_in[10];
        conv_x_b   = (const float*)d_in[11];
        conv_z_w   = (const float*)d_in[12];
        conv_z_b   = (const float*)d_in[13];
        x_proj_w   = (const float*)d_in[14];
        ln_w       = (const float*)d_in[15];
        ln_b       = (const float*)d_in[16];
        dt_proj_w  = (const float*)d_in[17];
        dt_proj_b  = (const float*)d_in[18];
        A_log      = (const float*)d_in[19];
        D_param    = (const float*)d_in[20];
        out_proj_w = (const float*)d_in[21];
        for (int g = 0; g < 4; g++) {
            post_w[g] = (const float*)d_in[22 + 2 * g];
            post_b[g] = (const float*)d_in[23 + 2 * g];
        }
        gate_logits = (const float*)d_in[30];
    }
    float* out = (float*)d_out;

    const int SMEM_INNER = (12544 + 2352 + 12288) * 4;  // 108,736 B
    cudaFuncSetAttribute(mamba_inner, cudaFuncAttributeMaxDynamicSharedMemorySize, SMEM_INNER);
    cudaFuncSetAttribute(gemm_in_mma, cudaFuncAttributeMaxDynamicSharedMemorySize, SMEM_MMA);
    cudaFuncSetAttribute(gemm_out_mma, cudaFuncAttributeMaxDynamicSharedMemorySize, SMEM_MMA);

    bias_kernel<<<5, 512>>>(in_proj_w, pre_b[0], pre_b[1], pre_b[2], pre_b[3],
                            post_b[0], post_b[1], post_b[2], post_b[3], gate_logits);
    tok_split<<<12544, 256>>>(tokens);
    fuse_gemm_all<<<dim3(4, 4, 8), 256>>>(in_proj_w, pre_w[0], pre_w[1], pre_w[2], pre_w[3],
                                          out_proj_w, post_w[0], post_w[1], post_w[2], post_w[3],
                                          gate_logits);
    gemm_in_mma<<<dim3(4, 196, 4), 256, SMEM_MMA>>>();
    mamba_inner<<<2048, 256, SMEM_INNER>>>(conv_x_w, conv_x_b, conv_z_w, conv_z_b,
                                           x_proj_w, ln_w, ln_b, dt_proj_w, dt_proj_b,
                                           A_log, D_param);
    gemm_out_mma<<<dim3(4, 196), 256, SMEM_MMA>>>(out);
    (void)n_in; (void)out_size;
}

// round 14
// speedup vs baseline: 3.3098x; 1.2720x over previous
#include <cuda_runtime.h>
#include <cuda_fp16.h>
#include <math.h>
#include <stdint.h>

#define NPOS 49
#define DIMV 512
#define DHALF 256
#define EDIM 48
#define TOK_PER_G 25088            // 512*49
#define M_TOT 100352               // 2048*49
#define SLAB 12845056              // 25088*512 (elements)
#define WSZ 262144                 // 512*512

// ---------------- device scratch (no allocations allowed) ----------------
__device__ float g_xz[51380224];                     // (2048, 49, 512) fp32
__device__ __align__(16) __half g_tok_h[12845056];
__device__ __align__(16) __half g_tok_l[12845056];
__device__ __align__(16) __half g_yc_h[51380224];
__device__ __align__(16) __half g_yc_l[51380224];
__device__ __align__(16) __half g_xc_h[25690112];    // (2048*49, 256) x_conv hi
__device__ __align__(16) __half g_xc_l[25690112];    // x_conv lo
__device__ __align__(16) float  g_xdbl[4816896];     // (2048*49, 48) post-LN
__device__ __align__(16) __half g_Wc_h[4 * WSZ];
__device__ __align__(16) __half g_Wo_h[4 * WSZ];
__device__ __align__(16) __half g_xpw_h[12288];      // x_proj_w fp16
__device__ float g_bc[4 * DIMV];
__device__ float g_outb[DIMV];

__constant__ int c_diag[49] = {0,1,7,2,8,14,3,9,15,21,4,10,16,22,28,5,11,17,23,29,35,
                               6,12,18,24,30,36,42,13,19,25,31,37,43,20,26,32,38,44,
                               27,33,39,45,34,40,46,41,47,48};
__constant__ int c_anti[49] = {6,5,13,4,12,20,3,11,19,27,2,10,18,26,34,1,9,17,25,33,41,
                               0,8,16,24,32,40,48,7,15,23,31,39,47,14,22,30,38,46,
                               21,29,37,45,28,36,44,35,43,42};

// ---------------- mma.sync / cp.async helpers (baseline PTX, valid on sm_103) ----------------
__device__ __forceinline__ uint32_t smem_u32(const void* p) {
    uint32_t a;
    asm("{ .reg .u64 t; cvta.to.shared.u64 t, %1; cvt.u32.u64 %0, t; }" : "=r"(a) : "l"(p));
    return a;
}
__device__ __forceinline__ void ldsm_x4(uint32_t* r, uint32_t addr) {
    asm volatile("ldmatrix.sync.aligned.m8n8.x4.shared.b16 {%0,%1,%2,%3}, [%4];"
                 : "=r"(r[0]), "=r"(r[1]), "=r"(r[2]), "=r"(r[3]) : "r"(addr));
}
__device__ __forceinline__ void mma16816(float* c, const uint32_t* a, const uint32_t* b) {
    asm volatile(
        "mma.sync.aligned.m16n8k16.row.col.f32.f16.f16.f32 "
        "{%0,%1,%2,%3}, {%4,%5,%6,%7}, {%8,%9}, {%0,%1,%2,%3};"
        : "+f"(c[0]), "+f"(c[1]), "+f"(c[2]), "+f"(c[3])
        : "r"(a[0]), "r"(a[1]), "r"(a[2]), "r"(a[3]), "r"(b[0]), "r"(b[1]));
}
__device__ __forceinline__ void cpa16(uint32_t d, const void* s) {
    asm volatile("cp.async.cg.shared.global [%0], [%1], 16;" :: "r"(d), "l"(s));
}
#define CP_COMMIT() asm volatile("cp.async.commit_group;" ::: "memory")
#define CP_WAIT1()  asm volatile("cp.async.wait_group 1;" ::: "memory")
#define CP_WAIT0()  asm volatile("cp.async.wait_group 0;" ::: "memory")

// main GEMM smem per stage (bytes): Ah 0, Al 10240, Bh 20480; 3 stages
#define ST_STRIDE 30720
#define SMEM_MMA 92160
#define ROWB 80            // bytes per padded row (40 halves)

// ---------------- small prep kernels ----------------
__device__ __forceinline__ float gate_val(const float* gl, int g) {
    float m = fmaxf(fmaxf(gl[0], gl[1]), fmaxf(gl[2], gl[3]));
    float e0 = expf(gl[0] - m), e1 = expf(gl[1] - m), e2 = expf(gl[2] - m), e3 = expf(gl[3] - m);
    float s = e0 + e1 + e2 + e3;
    float eg = (g == 0) ? e0 : (g == 1) ? e1 : (g == 2) ? e2 : e3;
    return eg / s;
}

__global__ void bias_kernel(const float* __restrict__ in_proj_w,
                            const float* __restrict__ bh, const float* __restrict__ bv,
                            const float* __restrict__ bd, const float* __restrict__ ba,
                            const float* __restrict__ ph, const float* __restrict__ pv,
                            const float* __restrict__ pd, const float* __restrict__ pa,
                            const float* __restrict__ gl, const float* __restrict__ xpw) {
    int blk = blockIdx.x;
    int j = threadIdx.x;
    if (blk < 4) {
        const float* pb = (blk == 0) ? bh : (blk == 1) ? bv : (blk == 2) ? bd : ba;
        float s = 0.f;
        const float* row = in_proj_w + j * DIMV;
        for (int k = 0; k < DIMV; k++) s += row[k] * pb[k];
        g_bc[blk * DIMV + j] = s;
    } else if (blk == 4) {
        g_outb[j] = gate_val(gl, 0) * ph[j] + gate_val(gl, 1) * pv[j] +
                    gate_val(gl, 2) * pd[j] + gate_val(gl, 3) * pa[j];
    } else {
        for (int i = j; i < EDIM * DHALF; i += 512)
            g_xpw_h[i] = __float2half(xpw[i]);
    }
}

// tokens fp32 -> fp16 hi/lo
__global__ __launch_bounds__(256) void tok_split(const float* __restrict__ tk) {
    size_t i = ((size_t)blockIdx.x * 256 + threadIdx.x) * 4;
    float4 v = *(const float4*)(tk + i);
    __half h0 = __float2half(v.x), h1 = __float2half(v.y);
    __half h2 = __float2half(v.z), h3 = __float2half(v.w);
    __half l0 = __float2half(v.x - __half2float(h0));
    __half l1 = __float2half(v.y - __half2float(h1));
    __half l2 = __float2half(v.z - __half2float(h2));
    __half l3 = __float2half(v.w - __half2float(h3));
    *(__half2*)(g_tok_h + i)     = __half2(h0, h1);
    *(__half2*)(g_tok_h + i + 2) = __half2(h2, h3);
    *(__half2*)(g_tok_l + i)     = __half2(l0, l1);
    *(__half2*)(g_tok_l + i + 2) = __half2(l2, l3);
}

// ---------------- batched weight-fusion GEMM (8 products, one launch) ----------------
#define BKT 8
#define GEMM_COMPUTE(As, Bs, acc, tx, ty)                                     \
    _Pragma("unroll")                                                         \
    for (int kk = 0; kk < BKT; kk++) {                                        \
        float ar[8], br[8];                                                   \
        *(float4*)(ar)     = *(const float4*)&As[kk][(ty) * 8];               \
        *(float4*)(ar + 4) = *(const float4*)&As[kk][(ty) * 8 + 4];           \
        *(float4*)(br)     = *(const float4*)&Bs[kk][(tx) * 8];               \
        *(float4*)(br + 4) = *(const float4*)&Bs[kk][(tx) * 8 + 4];           \
        _Pragma("unroll")                                                     \
        for (int ii = 0; ii < 8; ii++)                                        \
            _Pragma("unroll")                                                 \
            for (int jj = 0; jj < 8; jj++) acc[ii][jj] += ar[ii] * br[jj];    \
    }

__global__ __launch_bounds__(256) void fuse_gemm_all(
    const float* __restrict__ in_proj, const float* __restrict__ p0,
    const float* __restrict__ p1, const float* __restrict__ p2, const float* __restrict__ p3,
    const float* __restrict__ outp, const float* __restrict__ q0,
    const float* __restrict__ q1, const float* __restrict__ q2, const float* __restrict__ q3,
    const float* __restrict__ gl) {
    __shared__ float As[BKT][128];
    __shared__ float Bs[BKT][128];
    int z = blockIdx.z;
    const float* A; const float* B;
    __half* Ch; float scale;
    if (z < 4) {
        A = in_proj;
        B = (z == 0) ? p0 : (z == 1) ? p1 : (z == 2) ? p2 : p3;
        Ch = g_Wc_h + z * WSZ; scale = 1.f;
    } else {
        int g = z - 4;
        A = (g == 0) ? q0 : (g == 1) ? q1 : (g == 2) ? q2 : q3;
        B = outp;
        Ch = g_Wo_h + g * WSZ; scale = gate_val(gl, g);
    }
    int tid = threadIdx.x;
    int n0 = blockIdx.x * 128, m0 = blockIdx.y * 128;
    int tx = tid & 15, ty = tid >> 4;
    int lr = tid >> 1, lk4 = (tid & 1) * 4;
    int bk = tid >> 5, bc4 = (tid & 31) * 4;
    float acc[8][8] = {};
    const float* Arow = A + (m0 + lr) * DIMV + lk4;

    float4 av = *(const float4*)(Arow);
    float4 bv = *(const float4*)(B + bk * DIMV + n0 + bc4);
    for (int k0 = 0; k0 < DIMV; k0 += BKT) {
        As[lk4 + 0][lr] = av.x; As[lk4 + 1][lr] = av.y;
        As[lk4 + 2][lr] = av.z; As[lk4 + 3][lr] = av.w;
        *(float4*)&Bs[bk][bc4] = bv;
        __syncthreads();
        int k1 = k0 + BKT;
        if (k1 < DIMV) {
            av = *(const float4*)(Arow + k1);
            bv = *(const float4*)(B + (k1 + bk) * DIMV + n0 + bc4);
        }
        GEMM_COMPUTE(As, Bs, acc, tx, ty)
        __syncthreads();
    }
    #pragma unroll
    for (int i = 0; i < 8; i++) {
        int row = m0 + ty * 8 + i;
        #pragma unroll
        for (int j = 0; j < 8; j++)
            Ch[row * DIMV + n0 + tx * 8 + j] = __float2half(acc[i][j] * scale);
    }
}

// ---------------- HMMA split-fp16 core: hi-pass then lo-pass (dep distance 4) ----------------
__device__ __forceinline__ void mma_chunk(uint32_t sbase, float acc[2][8][4],
                                          int wm, int wn, int l) {
    #pragma unroll
    for (int ks = 0; ks < 2; ks++) {
        int ko = ks * 32;  // bytes (16 halves)
        uint32_t ah[2][4], al[2][4];
        #pragma unroll
        for (int mt = 0; mt < 2; mt++) {
            int row = wm * 32 + mt * 16 + (l & 15);
            uint32_t ad = sbase + row * ROWB + ko + ((l >> 4) * 16);
            ldsm_x4(ah[mt], ad);
            ldsm_x4(al[mt], ad + 10240);
        }
        #pragma unroll
        for (int np = 0; np < 4; np++) {
            uint32_t bh4[4];
            int nrow = wn * 64 + np * 16 + (l & 7) + ((l >> 4) << 3);
            uint32_t bd = sbase + 20480 + nrow * ROWB + ko + (((l >> 3) & 1) * 16);
            ldsm_x4(bh4, bd);
            #pragma unroll
            for (int mt = 0; mt < 2; mt++)
                #pragma unroll
                for (int hf = 0; hf < 2; hf++)
                    mma16816(acc[mt][np * 2 + hf], ah[mt], &bh4[hf * 2]);
            #pragma unroll
            for (int mt = 0; mt < 2; mt++)
                #pragma unroll
                for (int hf = 0; hf < 2; hf++)
                    mma16816(acc[mt][np * 2 + hf], al[mt], &bh4[hf * 2]);
        }
    }
}

// Input GEMM: xz[g*25088+m, n] = sum_k tok[gather(m), k] * Wc_g[n, k] + bc_g[n]
__global__ __launch_bounds__(256, 2) void gemm_in_mma() {
    extern __shared__ char smem[];
    const int t = threadIdx.x;
    const int w = t >> 5, l = t & 31;
    const int wm = w & 3, wn = w >> 2;
    const int n0 = blockIdx.x * 128, m0 = blockIdx.y * 128, g = blockIdx.z;

    const int lr0 = t >> 2;
    const int seg = (t & 3) * 8;     // halves
    size_t aG[2], bG[2];
    #pragma unroll
    for (int p = 0; p < 2; p++) {
        int r = lr0 + p * 64;
        int m = m0 + r;
        int bi = m / NPOS, ll = m - bi * NPOS;
        int srcl = ll;
        if (g == 1) srcl = (ll % 7) * 7 + ll / 7;
        else if (g == 2) srcl = c_diag[ll];
        else if (g == 3) srcl = c_anti[ll];
        aG[p] = (size_t)(bi * NPOS + srcl) * DIMV + seg;
        bG[p] = (size_t)g * WSZ + (size_t)(n0 + r) * DIMV + seg;
    }
    const int sOff0 = (lr0 * 40 + seg) * 2;          // bytes
    const int sOff1 = ((lr0 + 64) * 40 + seg) * 2;
    const uint32_t sb32 = smem_u32(smem);

    float acc[2][8][4];
    #pragma unroll
    for (int i = 0; i < 2; i++)
        #pragma unroll
        for (int j = 0; j < 8; j++)
            #pragma unroll
            for (int q = 0; q < 4; q++) acc[i][j][q] = 0.f;

    #define ISSUE_IN(stage, c)                                                   \
        do {                                                                     \
            uint32_t st_ = sb32 + (stage) * ST_STRIDE;                           \
            int kc_ = (c) * 32;                                                  \
            cpa16(st_ + sOff0,         g_tok_h + aG[0] + kc_);                   \
            cpa16(st_ + sOff1,         g_tok_h + aG[1] + kc_);                   \
            cpa16(st_ + 10240 + sOff0, g_tok_l + aG[0] + kc_);                   \
            cpa16(st_ + 10240 + sOff1, g_tok_l + aG[1] + kc_);                   \
            cpa16(st_ + 20480 + sOff0, g_Wc_h + bG[0] + kc_);                    \
            cpa16(st_ + 20480 + sOff1, g_Wc_h + bG[1] + kc_);                    \
            CP_COMMIT();                                                         \
        } while (0)

    ISSUE_IN(0, 0);
    ISSUE_IN(1, 1);
    for (int c = 0; c < 16; c++) {
        if (c < 15) CP_WAIT1(); else CP_WAIT0();
        __syncthreads();
        if (c + 2 < 16) ISSUE_IN((c + 2) % 3, c + 2);
        mma_chunk(sb32 + (c % 3) * ST_STRIDE, acc, wm, wn, l);
    }
    #undef ISSUE_IN

    int lrow = l >> 2, lcol = (l & 3) * 2;
    #pragma unroll
    for (int mt = 0; mt < 2; mt++) {
        int m = m0 + wm * 32 + mt * 16 + lrow;
        float* dbase = g_xz + (size_t)(g * TOK_PER_G + m) * DIMV;
        #pragma unroll
        for (int nt = 0; nt < 8; nt++) {
            int n = n0 + wn * 64 + nt * 8 + lcol;
            float b0 = g_bc[g * DIMV + n], b1 = g_bc[g * DIMV + n + 1];
            dbase[n]              = acc[mt][nt][0] + b0;
            dbase[n + 1]          = acc[mt][nt][1] + b1;
            dbase[8 * DIMV + n]     = acc[mt][nt][2] + b0;
            dbase[8 * DIMV + n + 1] = acc[mt][nt][3] + b1;
        }
    }
}

// Output GEMM: out[m, n] = outb[n] + sum_g sum_k ycat[g*25088+m, k] * Wo_g[n, k]
__global__ __launch_bounds__(256, 2) void gemm_out_mma(float* __restrict__ out) {
    extern __shared__ char smem[];
    const int t = threadIdx.x;
    const int w = t >> 5, l = t & 31;
    const int wm = w & 3, wn = w >> 2;
    const int n0 = blockIdx.x * 128, m0 = blockIdx.y * 128;

    const int lr0 = t >> 2;
    const int seg = (t & 3) * 8;
    size_t aG[2], bG[2];
    #pragma unroll
    for (int p = 0; p < 2; p++) {
        int r = lr0 + p * 64;
        aG[p] = (size_t)(m0 + r) * DIMV + seg;
        bG[p] = (size_t)(n0 + r) * DIMV + seg;
    }
    const int sOff0 = (lr0 * 40 + seg) * 2;
    const int sOff1 = ((lr0 + 64) * 40 + seg) * 2;
    const uint32_t sb32 = smem_u32(smem);

    float acc[2][8][4];
    #pragma unroll
    for (int i = 0; i < 2; i++)
        #pragma unroll
        for (int j = 0; j < 8; j++)
            #pragma unroll
            for (int q = 0; q < 4; q++) acc[i][j][q] = 0.f;

    #define ISSUE_OUT(stage, c)                                                  \
        do {                                                                     \
            uint32_t st_ = sb32 + (stage) * ST_STRIDE;                           \
            size_t aS_ = (size_t)((c) >> 4) * SLAB + (size_t)((c) & 15) * 32;    \
            size_t bS_ = (size_t)((c) >> 4) * WSZ + (size_t)((c) & 15) * 32;     \
            cpa16(st_ + sOff0,         g_yc_h + aS_ + aG[0]);                    \
            cpa16(st_ + sOff1,         g_yc_h + aS_ + aG[1]);                    \
            cpa16(st_ + 10240 + sOff0, g_yc_l + aS_ + aG[0]);                    \
            cpa16(st_ + 10240 + sOff1, g_yc_l + aS_ + aG[1]);                    \
            cpa16(st_ + 20480 + sOff0, g_Wo_h + bS_ + bG[0]);                    \
            cpa16(st_ + 20480 + sOff1, g_Wo_h + bS_ + bG[1]);                    \
            CP_COMMIT();                                                         \
        } while (0)

    ISSUE_OUT(0, 0);
    ISSUE_OUT(1, 1);
    for (int c = 0; c < 64; c++) {
        if (c < 63) CP_WAIT1(); else CP_WAIT0();
        __syncthreads();
        if (c + 2 < 64) ISSUE_OUT((c + 2) % 3, c + 2);
        mma_chunk(sb32 + (c % 3) * ST_STRIDE, acc, wm, wn, l);
    }
    #undef ISSUE_OUT

    int lrow = l >> 2, lcol = (l & 3) * 2;
    #pragma unroll
    for (int mt = 0; mt < 2; mt++) {
        int m = m0 + wm * 32 + mt * 16 + lrow;
        float* dbase = out + (size_t)m * DIMV;
        #pragma unroll
        for (int nt = 0; nt < 8; nt++) {
            int n = n0 + wn * 64 + nt * 8 + lcol;
            float b0 = g_outb[n], b1 = g_outb[n + 1];
            dbase[n]              = acc[mt][nt][0] + b0;
            dbase[n + 1]          = acc[mt][nt][1] + b1;
            dbase[8 * DIMV + n]     = acc[mt][nt][2] + b0;
            dbase[8 * DIMV + n + 1] = acc[mt][nt][3] + b1;
        }
    }
}

// ---------------- kernel A: streaming depthwise conv + SiLU (no smem) ----------------
__global__ __launch_bounds__(256) void conv_stream(
    const float* __restrict__ cxw, const float* __restrict__ cxb,
    const float* __restrict__ czw, const float* __restrict__ czb) {
    int b = blockIdx.x;
    int t = threadIdx.x;
    const float* base = g_xz + (size_t)b * NPOS * DIMV;
    size_t xcbase = (size_t)b * NPOS * DHALF;
    size_t ybase  = (size_t)b * NPOS * DIMV;

    // x path
    {
        float w0 = cxw[t * 3], w1 = cxw[t * 3 + 1], w2 = cxw[t * 3 + 2], bb = cxb[t];
        const float* xb = base + t;
        float prev = 0.f, cur = xb[0];
        for (int l = 0; l < NPOS; l++) {
            float nxt = (l < NPOS - 1) ? xb[(size_t)(l + 1) * DIMV] : 0.f;
            float v = w0 * prev + w1 * cur + w2 * nxt + bb;
            v = v / (1.f + expf(-v));
            prev = cur; cur = nxt;
            size_t idx = xcbase + (size_t)l * DHALF + t;
            __half h = __float2half(v);
            g_xc_h[idx] = h;
            g_xc_l[idx] = __float2half(v - __half2float(h));
        }
    }
    // z path -> ycat z slots
    {
        float w0 = czw[t * 3], w1 = czw[t * 3 + 1], w2 = czw[t * 3 + 2], bb = czb[t];
        const float* zb = base + DHALF + t;
        float prev = 0.f, cur = zb[0];
        for (int l = 0; l < NPOS; l++) {
            float nxt = (l < NPOS - 1) ? zb[(size_t)(l + 1) * DIMV] : 0.f;
            float v = w0 * prev + w1 * cur + w2 * nxt + bb;
            v = v / (1.f + expf(-v));
            prev = cur; cur = nxt;
            size_t idx = ybase + (size_t)l * DIMV + DHALF + t;
            __half hz = __float2half(v);
            g_yc_h[idx] = hz;
            g_yc_l[idx] = __float2half(v - __half2float(hz));
        }
    }
}

// ---------------- kernel B: x_dbl HMMA GEMM (M=100352, N=48, K=256) + fused LayerNorm ----------------
// smem per stage: Ah 0 (128*80), Al 10240, Bh 20480 (48*80=3840); stride 24320; 3 stages
#define XD_STRIDE 24320
#define SMEM_XDBL 72960
__global__ __launch_bounds__(128) void xdbl_mma(const float* __restrict__ lnw,
                                                const float* __restrict__ lnb) {
    extern __shared__ char smem[];
    __shared__ float sln[96];
    const int t = threadIdx.x;
    const int wm = t >> 5, l = t & 31;
    const int m0 = blockIdx.x * 128;
    if (t < 96) sln[t] = (t < 48) ? lnw[t] : lnb[t - 48];

    const uint32_t sb32 = smem_u32(smem);
    float acc[2][6][4];
    #pragma unroll
    for (int i = 0; i < 2; i++)
        #pragma unroll
        for (int j = 0; j < 6; j++)
            #pragma unroll
            for (int q = 0; q < 4; q++) acc[i][j][q] = 0.f;

    #define ISSUE_XD(stage, c)                                                    \
        do {                                                                      \
            uint32_t st_ = sb32 + (stage) * XD_STRIDE;                            \
            int kc_ = (c) * 32;                                                   \
            const __half* ah_ = g_xc_h + (size_t)(m0 + t) * DHALF + kc_;          \
            const __half* al_ = g_xc_l + (size_t)(m0 + t) * DHALF + kc_;          \
            _Pragma("unroll")                                                     \
            for (int sg = 0; sg < 4; sg++) {                                      \
                cpa16(st_ + t * ROWB + sg * 16,         ah_ + sg * 8);            \
                cpa16(st_ + 10240 + t * ROWB + sg * 16, al_ + sg * 8);            \
            }                                                                     \
            if (t < 48) {                                                         \
                const __half* bh_ = g_xpw_h + t * DHALF + kc_;                    \
                _Pragma("unroll")                                                 \
                for (int sg = 0; sg < 4; sg++)                                    \
                    cpa16(st_ + 20480 + t * ROWB + sg * 16, bh_ + sg * 8);        \
            }                                                                     \
            CP_COMMIT();                                                          \
        } while (0)

    ISSUE_XD(0, 0);
    ISSUE_XD(1, 1);
    for (int c = 0; c < 8; c++) {
        if (c < 7) CP_WAIT1(); else CP_WAIT0();
        __syncthreads();
        if (c + 2 < 8) ISSUE_XD((c + 2) % 3, c + 2);
        uint32_t sbase = sb32 + (c % 3) * XD_STRIDE;
        #pragma unroll
        for (int ks = 0; ks < 2; ks++) {
            int ko = ks * 32;
            uint32_t ah[2][4], al[2][4];
            #pragma unroll
            for (int mt = 0; mt < 2; mt++) {
                int row = wm * 32 + mt * 16 + (l & 15);
                uint32_t ad = sbase + row * ROWB + ko + ((l >> 4) * 16);
                ldsm_x4(ah[mt], ad);
                ldsm_x4(al[mt], ad + 10240);
            }
            #pragma unroll
            for (int np = 0; np < 3; np++) {
                uint32_t bh4[4];
                int nrow = np * 16 + (l & 7) + ((l >> 4) << 3);
                uint32_t bd = sbase + 20480 + nrow * ROWB + ko + (((l >> 3) & 1) * 16);
                ldsm_x4(bh4, bd);
                #pragma unroll
                for (int mt = 0; mt < 2; mt++)
                    #pragma unroll
                    for (int hf = 0; hf < 2; hf++)
                        mma16816(acc[mt][np * 2 + hf], ah[mt], &bh4[hf * 2]);
                #pragma unroll
                for (int mt = 0; mt < 2; mt++)
                    #pragma unroll
                    for (int hf = 0; hf < 2; hf++)
                        mma16816(acc[mt][np * 2 + hf], al[mt], &bh4[hf * 2]);
            }
        }
    }
    #undef ISSUE_XD

    // fused LayerNorm over the 48-wide rows + store
    int lrow = l >> 2, lq = l & 3;
    #pragma unroll
    for (int mt = 0; mt < 2; mt++) {
        #pragma unroll
        for (int half = 0; half < 2; half++) {
            float v[12];
            #pragma unroll
            for (int nt = 0; nt < 6; nt++) {
                v[nt * 2]     = acc[mt][nt][half * 2];
                v[nt * 2 + 1] = acc[mt][nt][half * 2 + 1];
            }
            float s1 = 0.f, s2 = 0.f;
            #pragma unroll
            for (int i = 0; i < 12; i++) { s1 += v[i]; s2 += v[i] * v[i]; }
            s1 += __shfl_xor_sync(0xFFFFFFFFu, s1, 1);
            s2 += __shfl_xor_sync(0xFFFFFFFFu, s2, 1);
            s1 += __shfl_xor_sync(0xFFFFFFFFu, s1, 2);
            s2 += __shfl_xor_sync(0xFFFFFFFFu, s2, 2);
            float mean = s1 * (1.f / 48.f);
            float var = s2 * (1.f / 48.f) - mean * mean;
            float rs = rsqrtf(var + 1e-5f);
            int r = m0 + wm * 32 + mt * 16 + lrow + half * 8;
            float* drow = g_xdbl + (size_t)r * EDIM;
            #pragma unroll
            for (int nt = 0; nt < 6; nt++) {
                int c0 = nt * 8 + lq * 2;
                drow[c0]     = (v[nt * 2] - mean) * rs * sln[c0] + sln[48 + c0];
                drow[c0 + 1] = (v[nt * 2 + 1] - mean) * rs * sln[c0 + 1] + sln[48 + c0 + 1];
            }
        }
    }
}

// ---------------- kernel C: dt_proj + selective scan ----------------
#define SMEM_SCAN 59584   // (49*256 + 49*48) * 4
__global__ __launch_bounds__(256, 3) void scan_kernel(
    const float* __restrict__ dtw, const float* __restrict__ dtb,
    const float* __restrict__ Alog, const float* __restrict__ Dp) {
    extern __shared__ float sm[];
    float* sx   = sm;                 // [l][d] 49*256
    float* sdbl = sm + 12544;         // [l][e] 49*48
    int b = blockIdx.x;
    int t = threadIdx.x;
    size_t xcbase = (size_t)b * NPOS * DHALF;
    size_t ybase  = (size_t)b * NPOS * DIMV;

    for (int l = 0; l < NPOS; l++) {
        size_t idx = xcbase + (size_t)l * DHALF + t;
        sx[l * DHALF + t] = __half2float(g_xc_h[idx]) + __half2float(g_xc_l[idx]);
    }
    for (int i = t; i < NPOS * EDIM; i += 256)
        sdbl[i] = g_xdbl[(size_t)b * NPOS * EDIM + i];
    __syncthreads();

    float wreg[32];
    #pragma unroll
    for (int r = 0; r < 32; r += 4)
        *(float4*)&wreg[r] = *(const float4*)&dtw[t * 32 + r];
    float a[8];
    #pragma unroll
    for (int n = 0; n < 8; n++) a[n] = -expf(Alog[t * 8 + n]);
    float Dv = Dp[t], bias = dtb[t];
    float h[8] = {};
    for (int l = 0; l < NPOS; l++) {
        const float* rowp = &sdbl[l * EDIM];
        float u = sx[l * DHALF + t];
        float s = bias;
        #pragma unroll
        for (int r = 0; r < 32; r += 4) {
            float4 x4 = *(const float4*)&rowp[r];
            s += wreg[r] * x4.x + wreg[r + 1] * x4.y + wreg[r + 2] * x4.z + wreg[r + 3] * x4.w;
        }
        float dt = (s > 20.f) ? s : log1pf(expf(s));
        float y = 0.f;
        #pragma unroll
        for (int n = 0; n < 8; n++) {
            float Bn = rowp[32 + n], Cn = rowp[40 + n];
            h[n] = h[n] * expf(dt * a[n]) + dt * Bn * u;
            y += h[n] * Cn;
        }
        y += Dv * u;
        if (isnan(y)) y = 0.f;
        else if (y > 65000.f) y = 65000.f;
        else if (y < -65000.f) y = -65000.f;
        size_t idx = ybase + (size_t)l * DIMV + t;
        __half hy = __float2half(y);
        g_yc_h[idx] = hy;
        g_yc_l[idx] = __float2half(y - __half2float(hy));
    }
}

// ---------------- host launcher ----------------
extern "C" void kernel_launch(void* const* d_in, const int* in_sizes, int n_in,
                              void* d_out, int out_size) {
    int dict_order = (in_sizes[10] != 768);

    const float* tokens = (const float*)d_in[0];
    const float* pre_w[4], *pre_b[4], *post_w[4], *post_b[4];
    const float *in_proj_w, *conv_x_w, *conv_x_b, *conv_z_w, *conv_z_b;
    const float *x_proj_w, *ln_w, *ln_b, *dt_proj_w, *dt_proj_b;
    const float *A_log, *D_param, *out_proj_w, *gate_logits;

    for (int g = 0; g < 4; g++) {
        pre_w[g] = (const float*)d_in[1 + 2 * g];
        pre_b[g] = (const float*)d_in[2 + 2 * g];
    }
    if (dict_order) {
        for (int g = 0; g < 4; g++) {
            post_w[g] = (const float*)d_in[9 + 2 * g];
            post_b[g] = (const float*)d_in[10 + 2 * g];
        }
        in_proj_w  = (const float*)d_in[17];
        conv_x_w   = (const float*)d_in[18];
        conv_x_b   = (const float*)d_in[19];
        conv_z_w   = (const float*)d_in[20];
        conv_z_b   = (const float*)d_in[21];
        x_proj_w   = (const float*)d_in[22];
        ln_w       = (const float*)d_in[23];
        ln_b       = (const float*)d_in[24];
        dt_proj_w  = (const float*)d_in[25];
        dt_proj_b  = (const float*)d_in[26];
        A_log      = (const float*)d_in[27];
        D_param    = (const float*)d_in[28];
        out_proj_w = (const float*)d_in[29];
        gate_logits = (const float*)d_in[30];
    } else {
        in_proj_w  = (const float*)d_in[9];
        conv_x_w   = (const float*)d_in[10];
        conv_x_b   = (const float*)d_in[11];
        conv_z_w   = (const float*)d_in[12];
        conv_z_b   = (const float*)d_in[13];
        x_proj_w   = (const float*)d_in[14];
        ln_w       = (const float*)d_in[15];
        ln_b       = (const float*)d_in[16];
        dt_proj_w  = (const float*)d_in[17];
        dt_proj_b  = (const float*)d_in[18];
        A_log      = (const float*)d_in[19];
        D_param    = (const float*)d_in[20];
        out_proj_w = (const float*)d_in[21];
        for (int g = 0; g < 4; g++) {
            post_w[g] = (const float*)d_in[22 + 2 * g];
            post_b[g] = (const float*)d_in[23 + 2 * g];
        }
        gate_logits = (const float*)d_in[30];
    }
    float* out = (float*)d_out;

    cudaFuncSetAttribute(gemm_in_mma, cudaFuncAttributeMaxDynamicSharedMemorySize, SMEM_MMA);
    cudaFuncSetAttribute(gemm_out_mma, cudaFuncAttributeMaxDynamicSharedMemorySize, SMEM_MMA);
    cudaFuncSetAttribute(xdbl_mma, cudaFuncAttributeMaxDynamicSharedMemorySize, SMEM_XDBL);
    cudaFuncSetAttribute(scan_kernel, cudaFuncAttributeMaxDynamicSharedMemorySize, SMEM_SCAN);

    bias_kernel<<<6, 512>>>(in_proj_w, pre_b[0], pre_b[1], pre_b[2], pre_b[3],
                            post_b[0], post_b[1], post_b[2], post_b[3],
                            gate_logits, x_proj_w);
    tok_split<<<12544, 256>>>(tokens);
    fuse_gemm_all<<<dim3(4, 4, 8), 256>>>(in_proj_w, pre_w[0], pre_w[1], pre_w[2], pre_w[3],
                                          out_proj_w, post_w[0], post_w[1], post_w[2], post_w[3],
                                          gate_logits);
    gemm_in_mma<<<dim3(4, 196, 4), 256, SMEM_MMA>>>();
    conv_stream<<<2048, 256>>>(conv_x_w, conv_x_b, conv_z_w, conv_z_b);
    xdbl_mma<<<784, 128, SMEM_XDBL>>>(ln_w, ln_b);
    scan_kernel<<<2048, 256, SMEM_SCAN>>>(dt_proj_w, dt_proj_b, A_log, D_param);
    gemm_out_mma<<<dim3(4, 196), 256, SMEM_MMA>>>(out);
    (void)n_in; (void)out_size;
}